// round 5
// baseline (speedup 1.0000x reference)
#include <cuda_runtime.h>
#include <math.h>

// Problem constants
#define B_ 2
#define T_ 2048
#define D_ 1024
#define H_ 16
#define DH_ 64
#define NROW (B_ * T_)        // 4096
#define BH_ (B_ * H_)         // 32

// ---------------------------------------------------------------------------
// Scratch
// ---------------------------------------------------------------------------
__device__ float g_qkv[(size_t)NROW * 3 * D_];          // [4096, 3072]
__device__ float g_q[(size_t)BH_ * T_ * DH_];           // [32, 2048, 64]
__device__ float g_k[(size_t)BH_ * T_ * DH_];
__device__ float g_v[(size_t)BH_ * T_ * DH_];
__device__ float g_attn[(size_t)NROW * D_];             // [4096, 1024]

// ---------------------------------------------------------------------------
// tf32 helpers
// ---------------------------------------------------------------------------
__device__ __forceinline__ unsigned f2tf32(float x) {
    unsigned r;
    asm("cvt.rna.tf32.f32 %0, %1;" : "=r"(r) : "f"(x));
    return r;
}

__device__ __forceinline__ void mma_tf32(float* c,
                                         unsigned a0, unsigned a1, unsigned a2, unsigned a3,
                                         unsigned b0, unsigned b1) {
    asm volatile("mma.sync.aligned.m16n8k8.row.col.f32.tf32.tf32.f32 "
                 "{%0,%1,%2,%3}, {%4,%5,%6,%7}, {%8,%9}, {%0,%1,%2,%3};"
                 : "+f"(c[0]), "+f"(c[1]), "+f"(c[2]), "+f"(c[3])
                 : "r"(a0), "r"(a1), "r"(a2), "r"(a3), "r"(b0), "r"(b1));
}

// ---------------------------------------------------------------------------
// tf32 GEMM: C[M,N] = A[M,K] @ B[K,N] (+bias)
// Block 128x128, BK=32, 256 threads = 8 warps (2m x 4n), warp tile 64x32.
// B fragments hoisted per k-step so LDS latency is covered before the mmas.
// ---------------------------------------------------------------------------
__global__ void __launch_bounds__(256, 2)
gemm_tf32(const float* __restrict__ A, const float* __restrict__ B,
          const float* __restrict__ bias, float* __restrict__ C,
          int M, int N, int K)
{
    __shared__ unsigned As[128][36];
    __shared__ unsigned Bs[32][136];

    const int bm = blockIdx.y * 128;
    const int bn = blockIdx.x * 128;
    const int tid = threadIdx.x;
    const int lane = tid & 31;
    const int w = tid >> 5;
    const int lrow = lane >> 2;
    const int lk = lane & 3;
    const int wm = (w & 1) * 64;
    const int wn = (w >> 1) * 32;

    const int arow = tid >> 1;              // 0..127
    const int abase = (tid & 1) * 16;       // 0 or 16
    const int brow = tid >> 3;              // 0..31
    const int bcol = (tid & 7) * 16;        // 0..112

    const float* Aptr = A + (size_t)(bm + arow) * K + abase;
    const float* Bptr = B + (size_t)brow * N + bn + bcol;

    float acc[4][4][4];
#pragma unroll
    for (int mt = 0; mt < 4; mt++)
#pragma unroll
        for (int nt = 0; nt < 4; nt++)
#pragma unroll
            for (int i = 0; i < 4; i++) acc[mt][nt][i] = 0.0f;

    float4 ra[4], rb[4];
#pragma unroll
    for (int i = 0; i < 4; i++) {
        ra[i] = *(const float4*)(Aptr + i * 4);
        rb[i] = *(const float4*)(Bptr + i * 4);
    }

    for (int kt = 0; kt < K; kt += 32) {
#pragma unroll
        for (int i = 0; i < 4; i++) {
            uint4 ua = make_uint4(f2tf32(ra[i].x), f2tf32(ra[i].y),
                                  f2tf32(ra[i].z), f2tf32(ra[i].w));
            *(uint4*)&As[arow][abase + i * 4] = ua;
            uint4 ub = make_uint4(f2tf32(rb[i].x), f2tf32(rb[i].y),
                                  f2tf32(rb[i].z), f2tf32(rb[i].w));
            *(uint4*)&Bs[brow][bcol + i * 4] = ub;
        }
        __syncthreads();

        if (kt + 32 < K) {
#pragma unroll
            for (int i = 0; i < 4; i++) {
                ra[i] = *(const float4*)(Aptr + kt + 32 + i * 4);
                rb[i] = *(const float4*)(Bptr + (size_t)(kt + 32) * N + i * 4);
            }
        }

#pragma unroll
        for (int ks = 0; ks < 4; ks++) {
            const int k0 = ks * 8 + lk;
            unsigned af[4][4];
#pragma unroll
            for (int mt = 0; mt < 4; mt++) {
                const int row = wm + mt * 16 + lrow;
                af[mt][0] = As[row][k0];
                af[mt][1] = As[row + 8][k0];
                af[mt][2] = As[row][k0 + 4];
                af[mt][3] = As[row + 8][k0 + 4];
            }
            unsigned bf[4][2];
#pragma unroll
            for (int nt = 0; nt < 4; nt++) {
                const int n0 = wn + nt * 8 + lrow;
                bf[nt][0] = Bs[k0][n0];
                bf[nt][1] = Bs[k0 + 4][n0];
            }
#pragma unroll
            for (int nt = 0; nt < 4; nt++)
#pragma unroll
                for (int mt = 0; mt < 4; mt++)
                    mma_tf32(acc[mt][nt], af[mt][0], af[mt][1], af[mt][2], af[mt][3],
                             bf[nt][0], bf[nt][1]);
        }
        __syncthreads();
    }

#pragma unroll
    for (int mt = 0; mt < 4; mt++) {
        const int row0 = bm + wm + mt * 16 + lrow;
#pragma unroll
        for (int nt = 0; nt < 4; nt++) {
            const int col = bn + wn + nt * 8 + lk * 2;
            float bx = 0.f, by = 0.f;
            if (bias) { bx = bias[col]; by = bias[col + 1]; }
            *(float2*)&C[(size_t)row0 * N + col] =
                make_float2(acc[mt][nt][0] + bx, acc[mt][nt][1] + by);
            *(float2*)&C[(size_t)(row0 + 8) * N + col] =
                make_float2(acc[mt][nt][2] + bx, acc[mt][nt][3] + by);
        }
    }
}

// ---------------------------------------------------------------------------
// RoPE + split + transpose. q pre-scaled by 1/8.
// ---------------------------------------------------------------------------
__global__ void rope_split_kernel()
{
    const int idx = blockIdx.x * blockDim.x + threadIdx.x;
    const int d2 = idx & 31;
    const int t  = (idx >> 5) & (T_ - 1);
    const int bh = idx >> 16;
    const int h = bh & (H_ - 1);
    const int b = bh >> 4;

    const float* row = g_qkv + ((size_t)(b * T_ + t)) * (3 * D_) + h * DH_;
    const float q0 = row[d2];
    const float q1 = row[d2 + 32];
    const float k0 = row[D_ + d2];
    const float k1 = row[D_ + d2 + 32];
    const float v0 = row[2 * D_ + d2];
    const float v1 = row[2 * D_ + d2 + 32];

    const float inv = 1.0f / powf(10000.0f, (float)d2 * (1.0f / 32.0f));
    const float ang = (float)t * inv;
    float sn, cs;
    sincosf(ang, &sn, &cs);

    const size_t obase = ((size_t)bh * T_ + t) * DH_;
    g_q[obase + d2]      = (q0 * cs - q1 * sn) * 0.125f;
    g_q[obase + d2 + 32] = (q1 * cs + q0 * sn) * 0.125f;
    g_k[obase + d2]      = k0 * cs - k1 * sn;
    g_k[obase + d2 + 32] = k1 * cs + k0 * sn;
    g_v[obase + d2]      = v0;
    g_v[obase + d2 + 32] = v1;
}

// ---------------------------------------------------------------------------
// Tensor-core flash attention v2 (tf32 mma, fp32 softmax).
// Block = (128-row q tile, bh). 4 warps; warp w owns 32 q rows (2 m16 groups).
// K/V tiles of 64 keys. Heavy (high-qt) blocks scheduled first.
// smem u32: qs[128][68], ks[64][68], ps[128][68], vs[64][72].
// ---------------------------------------------------------------------------
#define QS_PAD 68
#define VS_PAD 72
#define ATTN_SMEM ((128 * QS_PAD + 64 * QS_PAD + 128 * QS_PAD + 64 * VS_PAD) * 4)

__global__ void __launch_bounds__(128)
attn_tc_kernel()
{
    extern __shared__ unsigned smu[];
    unsigned* qs = smu;                         // [128][68]
    unsigned* ks = qs + 128 * QS_PAD;           // [64][68]
    unsigned* ps = ks + 64 * QS_PAD;            // [128][68]
    unsigned* vs = ps + 128 * QS_PAD;           // [64][72]

    const int qt = (T_ / 128 - 1) - blockIdx.x;   // heavy blocks first
    const int bh = blockIdx.y;
    const int tid = threadIdx.x;
    const int lane = tid & 31;
    const int w = tid >> 5;
    const int lrow = lane >> 2;
    const int lk = lane & 3;
    const int wrow = w * 32;

    const float* Qb = g_q + ((size_t)bh * T_ + qt * 128) * DH_;
    const float* Kb = g_k + (size_t)bh * T_ * DH_;
    const float* Vb = g_v + (size_t)bh * T_ * DH_;

    // load Q tile 128x64 -> tf32 smem (16 iters of float4)
#pragma unroll
    for (int i = 0; i < 16; i++) {
        const int e = tid + i * 128;
        const int r = e >> 4;
        const int c = (e & 15) << 2;
        float4 q4 = *(const float4*)&Qb[r * 64 + c];
        uint4 u = make_uint4(f2tf32(q4.x), f2tf32(q4.y), f2tf32(q4.z), f2tf32(q4.w));
        *(uint4*)&qs[r * QS_PAD + c] = u;
    }

    float m[2][2], l[2][2];
    float oacc[2][8][4];
#pragma unroll
    for (int mg = 0; mg < 2; mg++) {
        m[mg][0] = -1e30f; m[mg][1] = -1e30f;
        l[mg][0] = 0.f;    l[mg][1] = 0.f;
#pragma unroll
        for (int nt = 0; nt < 8; nt++)
#pragma unroll
            for (int i = 0; i < 4; i++) oacc[mg][nt][i] = 0.f;
    }

    const int ktmax = 2 * qt + 1;
    for (int kt = 0; kt <= ktmax; kt++) {
        __syncthreads();   // previous PV readers of vs done (covers qs on iter 0)
#pragma unroll
        for (int i = 0; i < 8; i++) {
            const int e = tid + i * 128;
            const int r = e >> 4;
            const int c = (e & 15) << 2;
            float4 k4 = *(const float4*)(Kb + (size_t)(kt * 64 + r) * 64 + c);
            uint4 uk = make_uint4(f2tf32(k4.x), f2tf32(k4.y), f2tf32(k4.z), f2tf32(k4.w));
            *(uint4*)&ks[r * QS_PAD + c] = uk;
            float4 v4 = *(const float4*)(Vb + (size_t)(kt * 64 + r) * 64 + c);
            uint4 uv = make_uint4(f2tf32(v4.x), f2tf32(v4.y), f2tf32(v4.z), f2tf32(v4.w));
            *(uint4*)&vs[r * VS_PAD + c] = uv;
        }
        __syncthreads();

        // ---- S = Q @ K^T : warp computes 32 x 64 ----
        float sacc[2][8][4];
#pragma unroll
        for (int mg = 0; mg < 2; mg++)
#pragma unroll
            for (int nt = 0; nt < 8; nt++)
#pragma unroll
                for (int i = 0; i < 4; i++) sacc[mg][nt][i] = 0.f;

#pragma unroll
        for (int kc = 0; kc < 8; kc++) {
            const int k0 = kc * 8 + lk;
            unsigned af[2][4];
#pragma unroll
            for (int mg = 0; mg < 2; mg++) {
                const int r0 = (wrow + mg * 16 + lrow) * QS_PAD;
                af[mg][0] = qs[r0 + k0];
                af[mg][1] = qs[r0 + 8 * QS_PAD + k0];
                af[mg][2] = qs[r0 + k0 + 4];
                af[mg][3] = qs[r0 + 8 * QS_PAD + k0 + 4];
            }
            unsigned bf[8][2];
#pragma unroll
            for (int nt = 0; nt < 8; nt++) {
                const int n0 = (nt * 8 + lrow) * QS_PAD;
                bf[nt][0] = ks[n0 + k0];
                bf[nt][1] = ks[n0 + k0 + 4];
            }
#pragma unroll
            for (int nt = 0; nt < 8; nt++)
#pragma unroll
                for (int mg = 0; mg < 2; mg++)
                    mma_tf32(sacc[mg][nt], af[mg][0], af[mg][1], af[mg][2], af[mg][3],
                             bf[nt][0], bf[nt][1]);
        }

        // ---- causal mask (near-diagonal tiles only) ----
        if (kt * 64 + 63 > qt * 128 + wrow) {
#pragma unroll
            for (int mg = 0; mg < 2; mg++) {
                const int rg0 = qt * 128 + wrow + mg * 16 + lrow;
                const int rg1 = rg0 + 8;
#pragma unroll
                for (int nt = 0; nt < 8; nt++) {
                    const int cg = kt * 64 + nt * 8 + lk * 2;
                    if (cg > rg0)     sacc[mg][nt][0] = -1e30f;
                    if (cg + 1 > rg0) sacc[mg][nt][1] = -1e30f;
                    if (cg > rg1)     sacc[mg][nt][2] = -1e30f;
                    if (cg + 1 > rg1) sacc[mg][nt][3] = -1e30f;
                }
            }
        }

        // ---- online softmax per row group ----
#pragma unroll
        for (int mg = 0; mg < 2; mg++) {
            float tm0 = -1e30f, tm1 = -1e30f;
#pragma unroll
            for (int nt = 0; nt < 8; nt++) {
                tm0 = fmaxf(tm0, fmaxf(sacc[mg][nt][0], sacc[mg][nt][1]));
                tm1 = fmaxf(tm1, fmaxf(sacc[mg][nt][2], sacc[mg][nt][3]));
            }
            tm0 = fmaxf(tm0, __shfl_xor_sync(0xffffffffu, tm0, 1));
            tm0 = fmaxf(tm0, __shfl_xor_sync(0xffffffffu, tm0, 2));
            tm1 = fmaxf(tm1, __shfl_xor_sync(0xffffffffu, tm1, 1));
            tm1 = fmaxf(tm1, __shfl_xor_sync(0xffffffffu, tm1, 2));

            const float mn0 = fmaxf(m[mg][0], tm0);
            const float mn1 = fmaxf(m[mg][1], tm1);
            const float corr0 = __expf(m[mg][0] - mn0);
            const float corr1 = __expf(m[mg][1] - mn1);
            m[mg][0] = mn0; m[mg][1] = mn1;

            float sum0 = 0.f, sum1 = 0.f;
            const int pr0 = (wrow + mg * 16 + lrow) * QS_PAD;
            const int pr1 = pr0 + 8 * QS_PAD;
#pragma unroll
            for (int nt = 0; nt < 8; nt++) {
                const int c0 = nt * 8 + lk * 2;
                const float p00 = __expf(sacc[mg][nt][0] - mn0);
                const float p01 = __expf(sacc[mg][nt][1] - mn0);
                const float p10 = __expf(sacc[mg][nt][2] - mn1);
                const float p11 = __expf(sacc[mg][nt][3] - mn1);
                sum0 += p00 + p01;
                sum1 += p10 + p11;
                ps[pr0 + c0]     = f2tf32(p00);
                ps[pr0 + c0 + 1] = f2tf32(p01);
                ps[pr1 + c0]     = f2tf32(p10);
                ps[pr1 + c0 + 1] = f2tf32(p11);
            }
            sum0 += __shfl_xor_sync(0xffffffffu, sum0, 1);
            sum0 += __shfl_xor_sync(0xffffffffu, sum0, 2);
            sum1 += __shfl_xor_sync(0xffffffffu, sum1, 1);
            sum1 += __shfl_xor_sync(0xffffffffu, sum1, 2);
            l[mg][0] = l[mg][0] * corr0 + sum0;
            l[mg][1] = l[mg][1] * corr1 + sum1;

#pragma unroll
            for (int nt = 0; nt < 8; nt++) {
                oacc[mg][nt][0] *= corr0;
                oacc[mg][nt][1] *= corr0;
                oacc[mg][nt][2] *= corr1;
                oacc[mg][nt][3] *= corr1;
            }
        }
        __syncwarp();

        // ---- O += P @ V : warp 32 x 64 ----
#pragma unroll
        for (int kc = 0; kc < 8; kc++) {
            const int k0 = kc * 8 + lk;
            unsigned af[2][4];
#pragma unroll
            for (int mg = 0; mg < 2; mg++) {
                const int r0 = (wrow + mg * 16 + lrow) * QS_PAD;
                af[mg][0] = ps[r0 + k0];
                af[mg][1] = ps[r0 + 8 * QS_PAD + k0];
                af[mg][2] = ps[r0 + k0 + 4];
                af[mg][3] = ps[r0 + 8 * QS_PAD + k0 + 4];
            }
            unsigned bf[8][2];
#pragma unroll
            for (int nt = 0; nt < 8; nt++) {
                const int n0 = nt * 8 + lrow;
                bf[nt][0] = vs[k0 * VS_PAD + n0];
                bf[nt][1] = vs[(k0 + 4) * VS_PAD + n0];
            }
#pragma unroll
            for (int nt = 0; nt < 8; nt++)
#pragma unroll
                for (int mg = 0; mg < 2; mg++)
                    mma_tf32(oacc[mg][nt], af[mg][0], af[mg][1], af[mg][2], af[mg][3],
                             bf[nt][0], bf[nt][1]);
        }
    }

    // ---- epilogue ----
    const int b = bh >> 4;
    const int h = bh & (H_ - 1);
#pragma unroll
    for (int mg = 0; mg < 2; mg++) {
        const float il0 = 1.0f / l[mg][0];
        const float il1 = 1.0f / l[mg][1];
        const int t0 = qt * 128 + wrow + mg * 16 + lrow;
        const int t1 = t0 + 8;
        const size_t base0 = ((size_t)(b * T_ + t0)) * D_ + h * DH_;
        const size_t base1 = ((size_t)(b * T_ + t1)) * D_ + h * DH_;
#pragma unroll
        for (int nt = 0; nt < 8; nt++) {
            const int c0 = nt * 8 + lk * 2;
            *(float2*)&g_attn[base0 + c0] =
                make_float2(oacc[mg][nt][0] * il0, oacc[mg][nt][1] * il0);
            *(float2*)&g_attn[base1 + c0] =
                make_float2(oacc[mg][nt][2] * il1, oacc[mg][nt][3] * il1);
        }
    }
}

// ---------------------------------------------------------------------------
// kernel_launch
// ---------------------------------------------------------------------------
extern "C" void kernel_launch(void* const* d_in, const int* in_sizes, int n_in,
                              void* d_out, int out_size)
{
    (void)in_sizes; (void)n_in; (void)out_size;
    const float* x     = (const float*)d_in[0];
    const float* qkv_w = (const float*)d_in[2];
    const float* out_w = (const float*)d_in[3];
    const float* out_b = (const float*)d_in[4];
    float* out = (float*)d_out;

    void* p_qkv;
    void* p_attn;
    cudaGetSymbolAddress(&p_qkv, g_qkv);
    cudaGetSymbolAddress(&p_attn, g_attn);

    cudaFuncSetAttribute(attn_tc_kernel,
                         cudaFuncAttributeMaxDynamicSharedMemorySize, ATTN_SMEM);

    // 1) QKV projection (tf32 tensor cores)
    gemm_tf32<<<dim3((3 * D_) / 128, NROW / 128), 256>>>(
        x, qkv_w, nullptr, (float*)p_qkv, NROW, 3 * D_, D_);

    // 2) RoPE + split/transpose
    rope_split_kernel<<<(BH_ * T_ * 32) / 256, 256>>>();

    // 3) causal flash attention (tensor cores, 128-row q tiles)
    attn_tc_kernel<<<dim3(T_ / 128, BH_), 128, ATTN_SMEM>>>();

    // 4) output projection + bias (tf32 tensor cores)
    gemm_tf32<<<dim3(D_ / 128, NROW / 128), 256>>>(
        (const float*)p_attn, out_w, out_b, out, NROW, D_, D_);
}

// round 6
// speedup vs baseline: 1.0649x; 1.0649x over previous
#include <cuda_runtime.h>
#include <math.h>

// Problem constants
#define B_ 2
#define T_ 2048
#define D_ 1024
#define H_ 16
#define DH_ 64
#define NROW (B_ * T_)        // 4096
#define BH_ (B_ * H_)         // 32

// ---------------------------------------------------------------------------
// Scratch
// ---------------------------------------------------------------------------
__device__ float g_x [(size_t)NROW * D_];               // tf32-rounded x
__device__ float g_w1[(size_t)D_ * 3 * D_];             // tf32-rounded qkv_w
__device__ float g_w2[(size_t)D_ * D_];                 // tf32-rounded out_w
__device__ float g_qkv[(size_t)NROW * 3 * D_];          // [4096, 3072]
__device__ float g_q[(size_t)BH_ * T_ * DH_];           // [32, 2048, 64] tf32-rounded
__device__ float g_k[(size_t)BH_ * T_ * DH_];
__device__ float g_v[(size_t)BH_ * T_ * DH_];
__device__ float g_attn[(size_t)NROW * D_];             // [4096, 1024] tf32-rounded

// ---------------------------------------------------------------------------
// helpers
// ---------------------------------------------------------------------------
__device__ __forceinline__ unsigned f2tf32(float x) {
    unsigned r;
    asm("cvt.rna.tf32.f32 %0, %1;" : "=r"(r) : "f"(x));
    return r;
}
__device__ __forceinline__ float rtf(float x) { return __uint_as_float(f2tf32(x)); }

__device__ __forceinline__ void mma_tf32(float* c,
                                         unsigned a0, unsigned a1, unsigned a2, unsigned a3,
                                         unsigned b0, unsigned b1) {
    asm volatile("mma.sync.aligned.m16n8k8.row.col.f32.tf32.tf32.f32 "
                 "{%0,%1,%2,%3}, {%4,%5,%6,%7}, {%8,%9}, {%0,%1,%2,%3};"
                 : "+f"(c[0]), "+f"(c[1]), "+f"(c[2]), "+f"(c[3])
                 : "r"(a0), "r"(a1), "r"(a2), "r"(a3), "r"(b0), "r"(b1));
}

__device__ __forceinline__ void cp16(void* smem, const void* gmem) {
    unsigned s = (unsigned)__cvta_generic_to_shared(smem);
    asm volatile("cp.async.cg.shared.global [%0], [%1], 16;" :: "r"(s), "l"(gmem));
}
__device__ __forceinline__ void cp_commit() {
    asm volatile("cp.async.commit_group;");
}
__device__ __forceinline__ void cp_wait0() {
    asm volatile("cp.async.wait_group 0;");
}

// ---------------------------------------------------------------------------
// tf32 pre-rounding copy (n % 1024 == 0)
// ---------------------------------------------------------------------------
__global__ void round_tf32_kernel(const float* __restrict__ in, float* __restrict__ out)
{
    const int i = (blockIdx.x * blockDim.x + threadIdx.x) * 4;
    float4 v = *(const float4*)(in + i);
    uint4 u = make_uint4(f2tf32(v.x), f2tf32(v.y), f2tf32(v.z), f2tf32(v.w));
    *(uint4*)(out + i) = u;
}

// ---------------------------------------------------------------------------
// tf32 GEMM with cp.async double-buffered stages.
// C[M,N] = A[M,K] @ B[K,N] (+bias). Inputs MUST already be tf32-rounded.
// Block 128x128, BK=32, 256 threads = 8 warps (2m x 4n), warp tile 64x32.
// ---------------------------------------------------------------------------
__global__ void __launch_bounds__(256, 2)
gemm_tf32(const float* __restrict__ A, const float* __restrict__ B,
          const float* __restrict__ bias, float* __restrict__ C,
          int M, int N, int K)
{
    __shared__ float As[2][128][36];
    __shared__ float Bs[2][32][136];

    const int bm = blockIdx.y * 128;
    const int bn = blockIdx.x * 128;
    const int tid = threadIdx.x;
    const int lane = tid & 31;
    const int w = tid >> 5;
    const int lrow = lane >> 2;
    const int lk = lane & 3;
    const int wm = (w & 1) * 64;
    const int wn = (w >> 1) * 32;

    const int arow = tid >> 1;              // 0..127
    const int abase = (tid & 1) * 16;       // 0 or 16
    const int brow = tid >> 3;              // 0..31
    const int bcol = (tid & 7) * 16;        // 0..112

    const float* Aptr = A + (size_t)(bm + arow) * K + abase;
    const float* Bptr = B + (size_t)brow * N + bn + bcol;

    float acc[4][4][4];
#pragma unroll
    for (int mt = 0; mt < 4; mt++)
#pragma unroll
        for (int nt = 0; nt < 4; nt++)
#pragma unroll
            for (int i = 0; i < 4; i++) acc[mt][nt][i] = 0.0f;

    // issue stage for k-offset kt into buffer s
    const int ntiles = K / 32;
    {
#pragma unroll
        for (int i = 0; i < 4; i++) cp16(&As[0][arow][abase + i * 4], Aptr + i * 4);
#pragma unroll
        for (int i = 0; i < 4; i++) cp16(&Bs[0][brow][bcol + i * 4], Bptr + i * 4);
        cp_commit();
    }

    for (int t = 0; t < ntiles; t++) {
        const int s = t & 1;
        cp_wait0();
        __syncthreads();

        if (t + 1 < ntiles) {
            const int kn = (t + 1) * 32;
#pragma unroll
            for (int i = 0; i < 4; i++)
                cp16(&As[s ^ 1][arow][abase + i * 4], Aptr + kn + i * 4);
#pragma unroll
            for (int i = 0; i < 4; i++)
                cp16(&Bs[s ^ 1][brow][bcol + i * 4], Bptr + (size_t)kn * N + i * 4);
            cp_commit();
        }

        const unsigned* Au = (const unsigned*)As[s];
        const unsigned* Bu = (const unsigned*)Bs[s];
#pragma unroll
        for (int ks = 0; ks < 4; ks++) {
            const int k0 = ks * 8 + lk;
            unsigned af[4][4];
#pragma unroll
            for (int mt = 0; mt < 4; mt++) {
                const int row = wm + mt * 16 + lrow;
                af[mt][0] = Au[row * 36 + k0];
                af[mt][1] = Au[(row + 8) * 36 + k0];
                af[mt][2] = Au[row * 36 + k0 + 4];
                af[mt][3] = Au[(row + 8) * 36 + k0 + 4];
            }
            unsigned bf[4][2];
#pragma unroll
            for (int nt = 0; nt < 4; nt++) {
                const int n0 = wn + nt * 8 + lrow;
                bf[nt][0] = Bu[k0 * 136 + n0];
                bf[nt][1] = Bu[(k0 + 4) * 136 + n0];
            }
#pragma unroll
            for (int nt = 0; nt < 4; nt++)
#pragma unroll
                for (int mt = 0; mt < 4; mt++)
                    mma_tf32(acc[mt][nt], af[mt][0], af[mt][1], af[mt][2], af[mt][3],
                             bf[nt][0], bf[nt][1]);
        }
        __syncthreads();
    }

#pragma unroll
    for (int mt = 0; mt < 4; mt++) {
        const int row0 = bm + wm + mt * 16 + lrow;
#pragma unroll
        for (int nt = 0; nt < 4; nt++) {
            const int col = bn + wn + nt * 8 + lk * 2;
            float bx = 0.f, by = 0.f;
            if (bias) { bx = bias[col]; by = bias[col + 1]; }
            *(float2*)&C[(size_t)row0 * N + col] =
                make_float2(acc[mt][nt][0] + bx, acc[mt][nt][1] + by);
            *(float2*)&C[(size_t)(row0 + 8) * N + col] =
                make_float2(acc[mt][nt][2] + bx, acc[mt][nt][3] + by);
        }
    }
}

// ---------------------------------------------------------------------------
// RoPE + split + transpose; outputs tf32-rounded. q pre-scaled by 1/8.
// ---------------------------------------------------------------------------
__global__ void rope_split_kernel()
{
    const int idx = blockIdx.x * blockDim.x + threadIdx.x;
    const int d2 = idx & 31;
    const int t  = (idx >> 5) & (T_ - 1);
    const int bh = idx >> 16;
    const int h = bh & (H_ - 1);
    const int b = bh >> 4;

    const float* row = g_qkv + ((size_t)(b * T_ + t)) * (3 * D_) + h * DH_;
    const float q0 = row[d2];
    const float q1 = row[d2 + 32];
    const float k0 = row[D_ + d2];
    const float k1 = row[D_ + d2 + 32];
    const float v0 = row[2 * D_ + d2];
    const float v1 = row[2 * D_ + d2 + 32];

    const float inv = 1.0f / powf(10000.0f, (float)d2 * (1.0f / 32.0f));
    const float ang = (float)t * inv;
    float sn, cs;
    sincosf(ang, &sn, &cs);

    const size_t obase = ((size_t)bh * T_ + t) * DH_;
    g_q[obase + d2]      = rtf((q0 * cs - q1 * sn) * 0.125f);
    g_q[obase + d2 + 32] = rtf((q1 * cs + q0 * sn) * 0.125f);
    g_k[obase + d2]      = rtf(k0 * cs - k1 * sn);
    g_k[obase + d2 + 32] = rtf(k1 * cs + k0 * sn);
    g_v[obase + d2]      = rtf(v0);
    g_v[obase + d2 + 32] = rtf(v1);
}

// ---------------------------------------------------------------------------
// Tensor-core flash attention v3.
// Block = (128-row q tile, bh), 4 warps, 32 q rows/warp (2 m16 groups).
// P kept in registers; S C-fragments are shuffled into PV A-fragments
// (no ps smem). K/V tiles of 64 keys loaded via cp.async.
// smem: qs[128][68] + ks[64][68] + vs[64][72] = ~69KB -> 3 blocks/SM.
// ---------------------------------------------------------------------------
#define QS_PAD 68
#define VS_PAD 72
#define ATTN_SMEM ((128 * QS_PAD + 64 * QS_PAD + 64 * VS_PAD) * 4)

__global__ void __launch_bounds__(128, 3)
attn_tc_kernel()
{
    extern __shared__ float smf[];
    float* qs = smf;                           // [128][68]
    float* ks = qs + 128 * QS_PAD;             // [64][68]
    float* vs = ks + 64 * QS_PAD;              // [64][72]
    const unsigned* qsu = (const unsigned*)qs;
    const unsigned* ksu = (const unsigned*)ks;
    const unsigned* vsu = (const unsigned*)vs;

    const int qt = (T_ / 128 - 1) - blockIdx.x;   // heavy blocks first
    const int bh = blockIdx.y;
    const int tid = threadIdx.x;
    const int lane = tid & 31;
    const int w = tid >> 5;
    const int lrow = lane >> 2;
    const int lk = lane & 3;
    const int wrow = w * 32;
    const int srcA = 4 * lrow + (lk >> 1);        // shfl src for a0/a1
    const int srcB = srcA + 2;                    // shfl src for a2/a3
    const bool hi = (lk & 1);

    const float* Qb = g_q + ((size_t)bh * T_ + qt * 128) * DH_;
    const float* Kb = g_k + (size_t)bh * T_ * DH_;
    const float* Vb = g_v + (size_t)bh * T_ * DH_;

    // async-load Q tile 128x64 (pre-rounded tf32)
#pragma unroll
    for (int i = 0; i < 16; i++) {
        const int e = tid + i * 128;
        const int r = e >> 4;
        const int c = (e & 15) << 2;
        cp16(&qs[r * QS_PAD + c], &Qb[r * 64 + c]);
    }
    cp_commit();

    float m[2][2], l[2][2];
    float oacc[2][8][4];
#pragma unroll
    for (int mg = 0; mg < 2; mg++) {
        m[mg][0] = -1e30f; m[mg][1] = -1e30f;
        l[mg][0] = 0.f;    l[mg][1] = 0.f;
#pragma unroll
        for (int nt = 0; nt < 8; nt++)
#pragma unroll
            for (int i = 0; i < 4; i++) oacc[mg][nt][i] = 0.f;
    }

    const int ktmax = 2 * qt + 1;
    for (int kt = 0; kt <= ktmax; kt++) {
        __syncthreads();   // previous-iteration readers of ks/vs done
#pragma unroll
        for (int i = 0; i < 8; i++) {
            const int e = tid + i * 128;
            const int r = e >> 4;
            const int c = (e & 15) << 2;
            cp16(&ks[r * QS_PAD + c], Kb + (size_t)(kt * 64 + r) * 64 + c);
            cp16(&vs[r * VS_PAD + c], Vb + (size_t)(kt * 64 + r) * 64 + c);
        }
        cp_commit();
        cp_wait0();
        __syncthreads();

        // ---- S = Q @ K^T : warp computes 32 x 64 ----
        float sacc[2][8][4];
#pragma unroll
        for (int mg = 0; mg < 2; mg++)
#pragma unroll
            for (int nt = 0; nt < 8; nt++)
#pragma unroll
                for (int i = 0; i < 4; i++) sacc[mg][nt][i] = 0.f;

#pragma unroll
        for (int kc = 0; kc < 8; kc++) {
            const int k0 = kc * 8 + lk;
            unsigned af[2][4];
#pragma unroll
            for (int mg = 0; mg < 2; mg++) {
                const int r0 = (wrow + mg * 16 + lrow) * QS_PAD;
                af[mg][0] = qsu[r0 + k0];
                af[mg][1] = qsu[r0 + 8 * QS_PAD + k0];
                af[mg][2] = qsu[r0 + k0 + 4];
                af[mg][3] = qsu[r0 + 8 * QS_PAD + k0 + 4];
            }
            unsigned bf[8][2];
#pragma unroll
            for (int nt = 0; nt < 8; nt++) {
                const int n0 = (nt * 8 + lrow) * QS_PAD;
                bf[nt][0] = ksu[n0 + k0];
                bf[nt][1] = ksu[n0 + k0 + 4];
            }
#pragma unroll
            for (int nt = 0; nt < 8; nt++)
#pragma unroll
                for (int mg = 0; mg < 2; mg++)
                    mma_tf32(sacc[mg][nt], af[mg][0], af[mg][1], af[mg][2], af[mg][3],
                             bf[nt][0], bf[nt][1]);
        }

        // ---- causal mask (near-diagonal tiles only) ----
        if (kt * 64 + 63 > qt * 128 + wrow) {
#pragma unroll
            for (int mg = 0; mg < 2; mg++) {
                const int rg0 = qt * 128 + wrow + mg * 16 + lrow;
                const int rg1 = rg0 + 8;
#pragma unroll
                for (int nt = 0; nt < 8; nt++) {
                    const int cg = kt * 64 + nt * 8 + lk * 2;
                    if (cg > rg0)     sacc[mg][nt][0] = -1e30f;
                    if (cg + 1 > rg0) sacc[mg][nt][1] = -1e30f;
                    if (cg > rg1)     sacc[mg][nt][2] = -1e30f;
                    if (cg + 1 > rg1) sacc[mg][nt][3] = -1e30f;
                }
            }
        }

        // ---- online softmax; p stays in sacc regs (tf32-rounded) ----
#pragma unroll
        for (int mg = 0; mg < 2; mg++) {
            float tm0 = -1e30f, tm1 = -1e30f;
#pragma unroll
            for (int nt = 0; nt < 8; nt++) {
                tm0 = fmaxf(tm0, fmaxf(sacc[mg][nt][0], sacc[mg][nt][1]));
                tm1 = fmaxf(tm1, fmaxf(sacc[mg][nt][2], sacc[mg][nt][3]));
            }
            tm0 = fmaxf(tm0, __shfl_xor_sync(0xffffffffu, tm0, 1));
            tm0 = fmaxf(tm0, __shfl_xor_sync(0xffffffffu, tm0, 2));
            tm1 = fmaxf(tm1, __shfl_xor_sync(0xffffffffu, tm1, 1));
            tm1 = fmaxf(tm1, __shfl_xor_sync(0xffffffffu, tm1, 2));

            const float mn0 = fmaxf(m[mg][0], tm0);
            const float mn1 = fmaxf(m[mg][1], tm1);
            const float corr0 = __expf(m[mg][0] - mn0);
            const float corr1 = __expf(m[mg][1] - mn1);
            m[mg][0] = mn0; m[mg][1] = mn1;

            float sum0 = 0.f, sum1 = 0.f;
#pragma unroll
            for (int nt = 0; nt < 8; nt++) {
                const float p00 = __expf(sacc[mg][nt][0] - mn0);
                const float p01 = __expf(sacc[mg][nt][1] - mn0);
                const float p10 = __expf(sacc[mg][nt][2] - mn1);
                const float p11 = __expf(sacc[mg][nt][3] - mn1);
                sum0 += p00 + p01;
                sum1 += p10 + p11;
                sacc[mg][nt][0] = __uint_as_float(f2tf32(p00));
                sacc[mg][nt][1] = __uint_as_float(f2tf32(p01));
                sacc[mg][nt][2] = __uint_as_float(f2tf32(p10));
                sacc[mg][nt][3] = __uint_as_float(f2tf32(p11));
            }
            sum0 += __shfl_xor_sync(0xffffffffu, sum0, 1);
            sum0 += __shfl_xor_sync(0xffffffffu, sum0, 2);
            sum1 += __shfl_xor_sync(0xffffffffu, sum1, 1);
            sum1 += __shfl_xor_sync(0xffffffffu, sum1, 2);
            l[mg][0] = l[mg][0] * corr0 + sum0;
            l[mg][1] = l[mg][1] * corr1 + sum1;

#pragma unroll
            for (int nt = 0; nt < 8; nt++) {
                oacc[mg][nt][0] *= corr0;
                oacc[mg][nt][1] *= corr0;
                oacc[mg][nt][2] *= corr1;
                oacc[mg][nt][3] *= corr1;
            }
        }

        // ---- O += P @ V : A-fragments built from sacc via shuffles ----
#pragma unroll
        for (int kc = 0; kc < 8; kc++) {
            unsigned af[2][4];
#pragma unroll
            for (int mg = 0; mg < 2; mg++) {
                const float v00 = __shfl_sync(0xffffffffu, sacc[mg][kc][0], srcA);
                const float v01 = __shfl_sync(0xffffffffu, sacc[mg][kc][1], srcA);
                const float v02 = __shfl_sync(0xffffffffu, sacc[mg][kc][2], srcA);
                const float v03 = __shfl_sync(0xffffffffu, sacc[mg][kc][3], srcA);
                const float w00 = __shfl_sync(0xffffffffu, sacc[mg][kc][0], srcB);
                const float w01 = __shfl_sync(0xffffffffu, sacc[mg][kc][1], srcB);
                const float w02 = __shfl_sync(0xffffffffu, sacc[mg][kc][2], srcB);
                const float w03 = __shfl_sync(0xffffffffu, sacc[mg][kc][3], srcB);
                af[mg][0] = __float_as_uint(hi ? v01 : v00);
                af[mg][1] = __float_as_uint(hi ? v03 : v02);
                af[mg][2] = __float_as_uint(hi ? w01 : w00);
                af[mg][3] = __float_as_uint(hi ? w03 : w02);
            }
            const int k0 = kc * 8 + lk;
            unsigned bf[8][2];
#pragma unroll
            for (int nt = 0; nt < 8; nt++) {
                const int n0 = nt * 8 + lrow;
                bf[nt][0] = vsu[k0 * VS_PAD + n0];
                bf[nt][1] = vsu[(k0 + 4) * VS_PAD + n0];
            }
#pragma unroll
            for (int nt = 0; nt < 8; nt++)
#pragma unroll
                for (int mg = 0; mg < 2; mg++)
                    mma_tf32(oacc[mg][nt], af[mg][0], af[mg][1], af[mg][2], af[mg][3],
                             bf[nt][0], bf[nt][1]);
        }
    }

    // ---- epilogue (tf32-rounded for the cp.async out-proj gemm) ----
    const int b = bh >> 4;
    const int h = bh & (H_ - 1);
#pragma unroll
    for (int mg = 0; mg < 2; mg++) {
        const float il0 = 1.0f / l[mg][0];
        const float il1 = 1.0f / l[mg][1];
        const int t0 = qt * 128 + wrow + mg * 16 + lrow;
        const int t1 = t0 + 8;
        const size_t base0 = ((size_t)(b * T_ + t0)) * D_ + h * DH_;
        const size_t base1 = ((size_t)(b * T_ + t1)) * D_ + h * DH_;
#pragma unroll
        for (int nt = 0; nt < 8; nt++) {
            const int c0 = nt * 8 + lk * 2;
            *(float2*)&g_attn[base0 + c0] =
                make_float2(rtf(oacc[mg][nt][0] * il0), rtf(oacc[mg][nt][1] * il0));
            *(float2*)&g_attn[base1 + c0] =
                make_float2(rtf(oacc[mg][nt][2] * il1), rtf(oacc[mg][nt][3] * il1));
        }
    }
}

// ---------------------------------------------------------------------------
// kernel_launch
// ---------------------------------------------------------------------------
extern "C" void kernel_launch(void* const* d_in, const int* in_sizes, int n_in,
                              void* d_out, int out_size)
{
    (void)in_sizes; (void)n_in; (void)out_size;
    const float* x     = (const float*)d_in[0];
    const float* qkv_w = (const float*)d_in[2];
    const float* out_w = (const float*)d_in[3];
    const float* out_b = (const float*)d_in[4];
    float* out = (float*)d_out;

    void *p_x, *p_w1, *p_w2, *p_qkv, *p_attn;
    cudaGetSymbolAddress(&p_x, g_x);
    cudaGetSymbolAddress(&p_w1, g_w1);
    cudaGetSymbolAddress(&p_w2, g_w2);
    cudaGetSymbolAddress(&p_qkv, g_qkv);
    cudaGetSymbolAddress(&p_attn, g_attn);

    cudaFuncSetAttribute(attn_tc_kernel,
                         cudaFuncAttributeMaxDynamicSharedMemorySize, ATTN_SMEM);

    // 0) tf32 pre-rounding of gemm inputs
    round_tf32_kernel<<<(NROW * D_) / 1024, 256>>>(x, (float*)p_x);
    round_tf32_kernel<<<(D_ * 3 * D_) / 1024, 256>>>(qkv_w, (float*)p_w1);
    round_tf32_kernel<<<(D_ * D_) / 1024, 256>>>(out_w, (float*)p_w2);

    // 1) QKV projection
    gemm_tf32<<<dim3((3 * D_) / 128, NROW / 128), 256>>>(
        (const float*)p_x, (const float*)p_w1, nullptr, (float*)p_qkv,
        NROW, 3 * D_, D_);

    // 2) RoPE + split/transpose (tf32-rounded outputs)
    rope_split_kernel<<<(BH_ * T_ * 32) / 256, 256>>>();

    // 3) causal flash attention (tensor cores, shfl-P, cp.async)
    attn_tc_kernel<<<dim3(T_ / 128, BH_), 128, ATTN_SMEM>>>();

    // 4) output projection + bias
    gemm_tf32<<<dim3(D_ / 128, NROW / 128), 256>>>(
        (const float*)p_attn, (const float*)p_w2, out_b, out, NROW, D_, D_);
}

// round 7
// speedup vs baseline: 1.9664x; 1.8465x over previous
#include <cuda_runtime.h>
#include <cuda_fp16.h>
#include <math.h>

// Problem constants
#define B_ 2
#define T_ 2048
#define D_ 1024
#define H_ 16
#define DH_ 64
#define NROW (B_ * T_)        // 4096
#define BH_ (B_ * H_)         // 32

// ---------------------------------------------------------------------------
// Scratch
// ---------------------------------------------------------------------------
__device__ __half g_xh [(size_t)NROW * D_];             // fp16 x
__device__ __half g_w1t[(size_t)(3 * D_) * D_];         // fp16 qkv_w transposed [N][K]
__device__ __half g_w2t[(size_t)D_ * D_];               // fp16 out_w transposed [N][K]
__device__ float  g_qkv[(size_t)NROW * 3 * D_];         // [4096, 3072] f32
__device__ __half g_qh[(size_t)BH_ * T_ * DH_];         // [32, 2048, 64]
__device__ __half g_kh[(size_t)BH_ * T_ * DH_];
__device__ __half g_vh[(size_t)BH_ * T_ * DH_];
__device__ __half g_attnh[(size_t)NROW * D_];           // [4096, 1024] fp16

// ---------------------------------------------------------------------------
// helpers
// ---------------------------------------------------------------------------
__device__ __forceinline__ unsigned pack_h2(float a, float b) {
    __half2 h = __floats2half2_rn(a, b);
    return *(unsigned*)&h;
}

__device__ __forceinline__ void mma_f16(float* c,
                                        unsigned a0, unsigned a1, unsigned a2, unsigned a3,
                                        unsigned b0, unsigned b1) {
    asm volatile("mma.sync.aligned.m16n8k16.row.col.f32.f16.f16.f32 "
                 "{%0,%1,%2,%3}, {%4,%5,%6,%7}, {%8,%9}, {%0,%1,%2,%3};"
                 : "+f"(c[0]), "+f"(c[1]), "+f"(c[2]), "+f"(c[3])
                 : "r"(a0), "r"(a1), "r"(a2), "r"(a3), "r"(b0), "r"(b1));
}

__device__ __forceinline__ void cp16(void* smem, const void* gmem) {
    unsigned s = (unsigned)__cvta_generic_to_shared(smem);
    asm volatile("cp.async.cg.shared.global [%0], [%1], 16;" :: "r"(s), "l"(gmem));
}
__device__ __forceinline__ void cp_commit() { asm volatile("cp.async.commit_group;"); }
__device__ __forceinline__ void cp_wait0()  { asm volatile("cp.async.wait_group 0;"); }

__device__ __forceinline__ void ldsm_x4_trans(unsigned& r0, unsigned& r1,
                                              unsigned& r2, unsigned& r3,
                                              const void* p) {
    unsigned s = (unsigned)__cvta_generic_to_shared(p);
    asm volatile("ldmatrix.sync.aligned.m8n8.x4.trans.shared.b16 {%0,%1,%2,%3}, [%4];"
                 : "=r"(r0), "=r"(r1), "=r"(r2), "=r"(r3) : "r"(s));
}

// ---------------------------------------------------------------------------
// prep kernels
// ---------------------------------------------------------------------------
__global__ void to_half_kernel(const float* __restrict__ in, __half* __restrict__ out)
{
    const int i = (blockIdx.x * blockDim.x + threadIdx.x) * 4;
    float4 v = *(const float4*)(in + i);
    *(__half2*)&out[i]     = __floats2half2_rn(v.x, v.y);
    *(__half2*)&out[i + 2] = __floats2half2_rn(v.z, v.w);
}

// in f32 [K][N] -> out fp16 [N][K]
__global__ void transpose_to_half(const float* __restrict__ in, __half* __restrict__ out,
                                  int K, int N)
{
    __shared__ float tile[32][33];
    const int n0 = blockIdx.x * 32;
    const int k0 = blockIdx.y * 32;
    const int tx = threadIdx.x;
    const int ty = threadIdx.y;
#pragma unroll
    for (int j = 0; j < 4; j++)
        tile[ty + 8 * j][tx] = in[(size_t)(k0 + ty + 8 * j) * N + n0 + tx];
    __syncthreads();
#pragma unroll
    for (int j = 0; j < 4; j++)
        out[(size_t)(n0 + ty + 8 * j) * K + k0 + tx] = __float2half(tile[tx][ty + 8 * j]);
}

// ---------------------------------------------------------------------------
// fp16 GEMM: C[M,N](f32) = A[M,K](fp16 row-major) @ Bt[N,K](fp16) (+bias)
// Block 128x128, BK=64, 256 threads = 8 warps (2m x 4n), warp tile 64x32.
// cp.async double-buffered. Pitch 72 halfs (16B-aligned rows, conflict-free).
// ---------------------------------------------------------------------------
#define GP 72
#define GEMM_SMEM (4 * 128 * GP * 2)   // 2 stages x (A + B) tiles, bytes

__global__ void __launch_bounds__(256, 2)
gemm_fp16(const __half* __restrict__ A, const __half* __restrict__ Bt,
          const float* __restrict__ bias, float* __restrict__ C,
          int M, int N, int K)
{
    extern __shared__ __half sh[];
    __half* Asm = sh;                    // [2][128][GP]
    __half* Bsm = sh + 2 * 128 * GP;     // [2][128][GP]

    const int bm = blockIdx.y * 128;
    const int bn = blockIdx.x * 128;
    const int tid = threadIdx.x;
    const int lane = tid & 31;
    const int w = tid >> 5;
    const int lrow = lane >> 2;
    const int lk = lane & 3;
    const int wm = (w & 1) * 64;
    const int wn = (w >> 1) * 32;

    const int srow = tid >> 1;              // 0..127
    const int sbase = (tid & 1) * 32;       // 0 or 32 (halfs)

    const __half* Aptr = A + (size_t)(bm + srow) * K + sbase;
    const __half* Bptr = Bt + (size_t)(bn + srow) * K + sbase;
    __half* Adst = Asm + srow * GP + sbase;
    __half* Bdst = Bsm + srow * GP + sbase;

    float acc[4][4][4];
#pragma unroll
    for (int mt = 0; mt < 4; mt++)
#pragma unroll
        for (int nt = 0; nt < 4; nt++)
#pragma unroll
            for (int i = 0; i < 4; i++) acc[mt][nt][i] = 0.0f;

    const int ntiles = K / 64;
    {
#pragma unroll
        for (int i = 0; i < 4; i++) cp16(Adst + i * 8, Aptr + i * 8);
#pragma unroll
        for (int i = 0; i < 4; i++) cp16(Bdst + i * 8, Bptr + i * 8);
        cp_commit();
    }

    for (int t = 0; t < ntiles; t++) {
        const int s = t & 1;
        cp_wait0();
        __syncthreads();

        if (t + 1 < ntiles) {
            const int kn = (t + 1) * 64;
            const int so = (s ^ 1) * 128 * GP;
#pragma unroll
            for (int i = 0; i < 4; i++) cp16(Adst + so + i * 8, Aptr + kn + i * 8);
#pragma unroll
            for (int i = 0; i < 4; i++) cp16(Bdst + so + i * 8, Bptr + kn + i * 8);
            cp_commit();
        }

        const __half* Ah = Asm + s * 128 * GP;
        const __half* Bh = Bsm + s * 128 * GP;
#pragma unroll
        for (int kc = 0; kc < 4; kc++) {
            const int kh = kc * 16 + 2 * lk;
            unsigned af[4][4];
#pragma unroll
            for (int mt = 0; mt < 4; mt++) {
                const int row = wm + mt * 16 + lrow;
                af[mt][0] = *(const unsigned*)&Ah[row * GP + kh];
                af[mt][1] = *(const unsigned*)&Ah[(row + 8) * GP + kh];
                af[mt][2] = *(const unsigned*)&Ah[row * GP + kh + 8];
                af[mt][3] = *(const unsigned*)&Ah[(row + 8) * GP + kh + 8];
            }
            unsigned bf[4][2];
#pragma unroll
            for (int nt = 0; nt < 4; nt++) {
                const int n0 = wn + nt * 8 + lrow;
                bf[nt][0] = *(const unsigned*)&Bh[n0 * GP + kh];
                bf[nt][1] = *(const unsigned*)&Bh[n0 * GP + kh + 8];
            }
#pragma unroll
            for (int nt = 0; nt < 4; nt++)
#pragma unroll
                for (int mt = 0; mt < 4; mt++)
                    mma_f16(acc[mt][nt], af[mt][0], af[mt][1], af[mt][2], af[mt][3],
                            bf[nt][0], bf[nt][1]);
        }
        __syncthreads();
    }

#pragma unroll
    for (int mt = 0; mt < 4; mt++) {
        const int row0 = bm + wm + mt * 16 + lrow;
#pragma unroll
        for (int nt = 0; nt < 4; nt++) {
            const int col = bn + wn + nt * 8 + lk * 2;
            float bx = 0.f, by = 0.f;
            if (bias) { bx = bias[col]; by = bias[col + 1]; }
            *(float2*)&C[(size_t)row0 * N + col] =
                make_float2(acc[mt][nt][0] + bx, acc[mt][nt][1] + by);
            *(float2*)&C[(size_t)(row0 + 8) * N + col] =
                make_float2(acc[mt][nt][2] + bx, acc[mt][nt][3] + by);
        }
    }
}

// ---------------------------------------------------------------------------
// RoPE + split + transpose -> fp16. q pre-scaled by 1/8.
// ---------------------------------------------------------------------------
__global__ void rope_split_kernel()
{
    const int idx = blockIdx.x * blockDim.x + threadIdx.x;
    const int d2 = idx & 31;
    const int t  = (idx >> 5) & (T_ - 1);
    const int bh = idx >> 16;
    const int h = bh & (H_ - 1);
    const int b = bh >> 4;

    const float* row = g_qkv + ((size_t)(b * T_ + t)) * (3 * D_) + h * DH_;
    const float q0 = row[d2];
    const float q1 = row[d2 + 32];
    const float k0 = row[D_ + d2];
    const float k1 = row[D_ + d2 + 32];
    const float v0 = row[2 * D_ + d2];
    const float v1 = row[2 * D_ + d2 + 32];

    const float inv = 1.0f / powf(10000.0f, (float)d2 * (1.0f / 32.0f));
    const float ang = (float)t * inv;
    float sn, cs;
    sincosf(ang, &sn, &cs);

    const size_t obase = ((size_t)bh * T_ + t) * DH_;
    g_qh[obase + d2]      = __float2half((q0 * cs - q1 * sn) * 0.125f);
    g_qh[obase + d2 + 32] = __float2half((q1 * cs + q0 * sn) * 0.125f);
    g_kh[obase + d2]      = __float2half(k0 * cs - k1 * sn);
    g_kh[obase + d2 + 32] = __float2half(k1 * cs + k0 * sn);
    g_vh[obase + d2]      = __float2half(v0);
    g_vh[obase + d2 + 32] = __float2half(v1);
}

// ---------------------------------------------------------------------------
// fp16 tensor-core flash attention.
// Block = (128-row q tile, bh), 4 warps, 32 q rows/warp (2 m16 groups).
// S = QK^T via m16n8k16 (K B-frags are contiguous half2 — no transpose).
// P: C-frag layout == A-frag layout in fp16 -> pack exp() to half2, no shfl.
// PV B-frags via ldmatrix.x4.trans on row-major V smem.
// smem: qs[128][72] + ks[64][72] + vs[64][72] fp16 = 36KB -> 3 blocks/SM.
// ---------------------------------------------------------------------------
#define AP 72
#define ATTN_SMEM ((128 * AP + 64 * AP + 64 * AP) * 2)

__global__ void __launch_bounds__(128, 3)
attn_fp16_kernel()
{
    extern __shared__ __half sh[];
    __half* qs = sh;                    // [128][72]
    __half* ks = qs + 128 * AP;         // [64][72]
    __half* vs = ks + 64 * AP;          // [64][72]

    const int qt = (T_ / 128 - 1) - blockIdx.x;   // heavy blocks first
    const int bh = blockIdx.y;
    const int tid = threadIdx.x;
    const int lane = tid & 31;
    const int w = tid >> 5;
    const int lrow = lane >> 2;
    const int lk = lane & 3;
    const int wrow = w * 32;

    const __half* Qb = g_qh + ((size_t)bh * T_ + qt * 128) * DH_;
    const __half* Kb = g_kh + (size_t)bh * T_ * DH_;
    const __half* Vb = g_vh + (size_t)bh * T_ * DH_;

    // stage Q tile 128x64 fp16 (8 chunks of 16B per row)
#pragma unroll
    for (int i = 0; i < 8; i++) {
        const int e = tid + i * 128;      // 0..1023
        const int r = e >> 3;
        const int c = (e & 7) * 8;
        cp16(&qs[r * AP + c], &Qb[r * 64 + c]);
    }
    cp_commit();

    float m[2][2], l[2][2];
    float oacc[2][8][4];
#pragma unroll
    for (int mg = 0; mg < 2; mg++) {
        m[mg][0] = -1e30f; m[mg][1] = -1e30f;
        l[mg][0] = 0.f;    l[mg][1] = 0.f;
#pragma unroll
        for (int nt = 0; nt < 8; nt++)
#pragma unroll
            for (int i = 0; i < 4; i++) oacc[mg][nt][i] = 0.f;
    }

    const int ktmax = 2 * qt + 1;
    for (int kt = 0; kt <= ktmax; kt++) {
        __syncthreads();   // previous-iteration readers of ks/vs done
#pragma unroll
        for (int i = 0; i < 4; i++) {
            const int e = tid + i * 128;  // 0..511
            const int r = e >> 3;
            const int c = (e & 7) * 8;
            cp16(&ks[r * AP + c], Kb + (size_t)(kt * 64 + r) * 64 + c);
            cp16(&vs[r * AP + c], Vb + (size_t)(kt * 64 + r) * 64 + c);
        }
        cp_commit();
        cp_wait0();
        __syncthreads();

        // ---- S = Q @ K^T : warp computes 32 x 64 ----
        float sacc[2][8][4];
#pragma unroll
        for (int mg = 0; mg < 2; mg++)
#pragma unroll
            for (int nt = 0; nt < 8; nt++)
#pragma unroll
                for (int i = 0; i < 4; i++) sacc[mg][nt][i] = 0.f;

#pragma unroll
        for (int kc = 0; kc < 4; kc++) {
            const int kh = kc * 16 + 2 * lk;
            unsigned af[2][4];
#pragma unroll
            for (int mg = 0; mg < 2; mg++) {
                const int r0 = wrow + mg * 16 + lrow;
                af[mg][0] = *(const unsigned*)&qs[r0 * AP + kh];
                af[mg][1] = *(const unsigned*)&qs[(r0 + 8) * AP + kh];
                af[mg][2] = *(const unsigned*)&qs[r0 * AP + kh + 8];
                af[mg][3] = *(const unsigned*)&qs[(r0 + 8) * AP + kh + 8];
            }
            unsigned bf[8][2];
#pragma unroll
            for (int nt = 0; nt < 8; nt++) {
                const int n0 = nt * 8 + lrow;
                bf[nt][0] = *(const unsigned*)&ks[n0 * AP + kh];
                bf[nt][1] = *(const unsigned*)&ks[n0 * AP + kh + 8];
            }
#pragma unroll
            for (int nt = 0; nt < 8; nt++)
#pragma unroll
                for (int mg = 0; mg < 2; mg++)
                    mma_f16(sacc[mg][nt], af[mg][0], af[mg][1], af[mg][2], af[mg][3],
                            bf[nt][0], bf[nt][1]);
        }

        // ---- causal mask (near-diagonal tiles only) ----
        if (kt * 64 + 63 > qt * 128 + wrow) {
#pragma unroll
            for (int mg = 0; mg < 2; mg++) {
                const int rg0 = qt * 128 + wrow + mg * 16 + lrow;
                const int rg1 = rg0 + 8;
#pragma unroll
                for (int nt = 0; nt < 8; nt++) {
                    const int cg = kt * 64 + nt * 8 + lk * 2;
                    if (cg > rg0)     sacc[mg][nt][0] = -1e30f;
                    if (cg + 1 > rg0) sacc[mg][nt][1] = -1e30f;
                    if (cg > rg1)     sacc[mg][nt][2] = -1e30f;
                    if (cg + 1 > rg1) sacc[mg][nt][3] = -1e30f;
                }
            }
        }

        // ---- online softmax; pack P to half2 A-frags (no shuffles) ----
        unsigned pk01[2][8], pk23[2][8];
#pragma unroll
        for (int mg = 0; mg < 2; mg++) {
            float tm0 = -1e30f, tm1 = -1e30f;
#pragma unroll
            for (int nt = 0; nt < 8; nt++) {
                tm0 = fmaxf(tm0, fmaxf(sacc[mg][nt][0], sacc[mg][nt][1]));
                tm1 = fmaxf(tm1, fmaxf(sacc[mg][nt][2], sacc[mg][nt][3]));
            }
            tm0 = fmaxf(tm0, __shfl_xor_sync(0xffffffffu, tm0, 1));
            tm0 = fmaxf(tm0, __shfl_xor_sync(0xffffffffu, tm0, 2));
            tm1 = fmaxf(tm1, __shfl_xor_sync(0xffffffffu, tm1, 1));
            tm1 = fmaxf(tm1, __shfl_xor_sync(0xffffffffu, tm1, 2));

            const float mn0 = fmaxf(m[mg][0], tm0);
            const float mn1 = fmaxf(m[mg][1], tm1);
            const float corr0 = __expf(m[mg][0] - mn0);
            const float corr1 = __expf(m[mg][1] - mn1);
            m[mg][0] = mn0; m[mg][1] = mn1;

            float sum0 = 0.f, sum1 = 0.f;
#pragma unroll
            for (int nt = 0; nt < 8; nt++) {
                const float p00 = __expf(sacc[mg][nt][0] - mn0);
                const float p01 = __expf(sacc[mg][nt][1] - mn0);
                const float p10 = __expf(sacc[mg][nt][2] - mn1);
                const float p11 = __expf(sacc[mg][nt][3] - mn1);
                sum0 += p00 + p01;
                sum1 += p10 + p11;
                pk01[mg][nt] = pack_h2(p00, p01);
                pk23[mg][nt] = pack_h2(p10, p11);
            }
            sum0 += __shfl_xor_sync(0xffffffffu, sum0, 1);
            sum0 += __shfl_xor_sync(0xffffffffu, sum0, 2);
            sum1 += __shfl_xor_sync(0xffffffffu, sum1, 1);
            sum1 += __shfl_xor_sync(0xffffffffu, sum1, 2);
            l[mg][0] = l[mg][0] * corr0 + sum0;
            l[mg][1] = l[mg][1] * corr1 + sum1;

#pragma unroll
            for (int nt = 0; nt < 8; nt++) {
                oacc[mg][nt][0] *= corr0;
                oacc[mg][nt][1] *= corr0;
                oacc[mg][nt][2] *= corr1;
                oacc[mg][nt][3] *= corr1;
            }
        }

        // ---- O += P @ V : V B-frags via ldmatrix.trans ----
#pragma unroll
        for (int kc = 0; kc < 4; kc++) {
            const int g = lane >> 3;
            const int li = lane & 7;
            const int vrow = kc * 16 + (g & 1) * 8 + li;
#pragma unroll
            for (int ntp = 0; ntp < 4; ntp++) {
                const int vcol = ntp * 16 + (g >> 1) * 8;
                unsigned r0, r1, r2, r3;
                ldsm_x4_trans(r0, r1, r2, r3, &vs[vrow * AP + vcol]);
#pragma unroll
                for (int mg = 0; mg < 2; mg++) {
                    mma_f16(oacc[mg][ntp * 2],
                            pk01[mg][2 * kc], pk23[mg][2 * kc],
                            pk01[mg][2 * kc + 1], pk23[mg][2 * kc + 1], r0, r1);
                    mma_f16(oacc[mg][ntp * 2 + 1],
                            pk01[mg][2 * kc], pk23[mg][2 * kc],
                            pk01[mg][2 * kc + 1], pk23[mg][2 * kc + 1], r2, r3);
                }
            }
        }
    }

    // ---- epilogue -> fp16 g_attnh ----
    const int b = bh >> 4;
    const int h = bh & (H_ - 1);
#pragma unroll
    for (int mg = 0; mg < 2; mg++) {
        const float il0 = 1.0f / l[mg][0];
        const float il1 = 1.0f / l[mg][1];
        const int t0 = qt * 128 + wrow + mg * 16 + lrow;
        const int t1 = t0 + 8;
        const size_t base0 = ((size_t)(b * T_ + t0)) * D_ + h * DH_;
        const size_t base1 = ((size_t)(b * T_ + t1)) * D_ + h * DH_;
#pragma unroll
        for (int nt = 0; nt < 8; nt++) {
            const int c0 = nt * 8 + lk * 2;
            *(__half2*)&g_attnh[base0 + c0] =
                __floats2half2_rn(oacc[mg][nt][0] * il0, oacc[mg][nt][1] * il0);
            *(__half2*)&g_attnh[base1 + c0] =
                __floats2half2_rn(oacc[mg][nt][2] * il1, oacc[mg][nt][3] * il1);
        }
    }
}

// ---------------------------------------------------------------------------
// kernel_launch
// ---------------------------------------------------------------------------
extern "C" void kernel_launch(void* const* d_in, const int* in_sizes, int n_in,
                              void* d_out, int out_size)
{
    (void)in_sizes; (void)n_in; (void)out_size;
    const float* x     = (const float*)d_in[0];
    const float* qkv_w = (const float*)d_in[2];
    const float* out_w = (const float*)d_in[3];
    const float* out_b = (const float*)d_in[4];
    float* out = (float*)d_out;

    void *p_xh, *p_w1t, *p_w2t, *p_qkv, *p_attnh;
    cudaGetSymbolAddress(&p_xh, g_xh);
    cudaGetSymbolAddress(&p_w1t, g_w1t);
    cudaGetSymbolAddress(&p_w2t, g_w2t);
    cudaGetSymbolAddress(&p_qkv, g_qkv);
    cudaGetSymbolAddress(&p_attnh, g_attnh);

    cudaFuncSetAttribute(gemm_fp16,
                         cudaFuncAttributeMaxDynamicSharedMemorySize, GEMM_SMEM);
    cudaFuncSetAttribute(attn_fp16_kernel,
                         cudaFuncAttributeMaxDynamicSharedMemorySize, ATTN_SMEM);

    // 0) prep: x -> fp16, weights -> fp16 transposed [N][K]
    to_half_kernel<<<(NROW * D_) / 1024, 256>>>(x, (__half*)p_xh);
    transpose_to_half<<<dim3(3 * D_ / 32, D_ / 32), dim3(32, 8)>>>(
        qkv_w, (__half*)p_w1t, D_, 3 * D_);
    transpose_to_half<<<dim3(D_ / 32, D_ / 32), dim3(32, 8)>>>(
        out_w, (__half*)p_w2t, D_, D_);

    // 1) QKV projection (fp16 tensor cores)
    gemm_fp16<<<dim3((3 * D_) / 128, NROW / 128), 256, GEMM_SMEM>>>(
        (const __half*)p_xh, (const __half*)p_w1t, nullptr, (float*)p_qkv,
        NROW, 3 * D_, D_);

    // 2) RoPE + split/transpose -> fp16
    rope_split_kernel<<<(BH_ * T_ * 32) / 256, 256>>>();

    // 3) causal flash attention (fp16 tensor cores)
    attn_fp16_kernel<<<dim3(T_ / 128, BH_), 128, ATTN_SMEM>>>();

    // 4) output projection + bias
    gemm_fp16<<<dim3(D_ / 128, NROW / 128), 256, GEMM_SMEM>>>(
        (const __half*)p_attnh, (const __half*)p_w2t, out_b, out, NROW, D_, D_);
}

// round 8
// speedup vs baseline: 2.0629x; 1.0491x over previous
#include <cuda_runtime.h>
#include <cuda_fp16.h>
#include <math.h>

// Problem constants
#define B_ 2
#define T_ 2048
#define D_ 1024
#define H_ 16
#define DH_ 64
#define NROW (B_ * T_)        // 4096
#define BH_ (B_ * H_)         // 32

// ---------------------------------------------------------------------------
// Scratch
// ---------------------------------------------------------------------------
__device__ __half g_xh [(size_t)NROW * D_];             // fp16 x
__device__ __half g_w1t[(size_t)(3 * D_) * D_];         // fp16 qkv_w transposed [N][K]
__device__ __half g_w2t[(size_t)D_ * D_];               // fp16 out_w transposed [N][K]
__device__ float  g_qkv[(size_t)NROW * 3 * D_];         // [4096, 3072] f32
__device__ __half g_qh[(size_t)BH_ * T_ * DH_];         // [32, 2048, 64]
__device__ __half g_kh[(size_t)BH_ * T_ * DH_];
__device__ __half g_vh[(size_t)BH_ * T_ * DH_];
__device__ __half g_attnh[(size_t)NROW * D_];           // [4096, 1024] fp16

// ---------------------------------------------------------------------------
// helpers
// ---------------------------------------------------------------------------
__device__ __forceinline__ unsigned pack_h2(float a, float b) {
    __half2 h = __floats2half2_rn(a, b);
    return *(unsigned*)&h;
}

__device__ __forceinline__ void mma_f16(float* c,
                                        unsigned a0, unsigned a1, unsigned a2, unsigned a3,
                                        unsigned b0, unsigned b1) {
    asm volatile("mma.sync.aligned.m16n8k16.row.col.f32.f16.f16.f32 "
                 "{%0,%1,%2,%3}, {%4,%5,%6,%7}, {%8,%9}, {%0,%1,%2,%3};"
                 : "+f"(c[0]), "+f"(c[1]), "+f"(c[2]), "+f"(c[3])
                 : "r"(a0), "r"(a1), "r"(a2), "r"(a3), "r"(b0), "r"(b1));
}

__device__ __forceinline__ void cp16(void* smem, const void* gmem) {
    unsigned s = (unsigned)__cvta_generic_to_shared(smem);
    asm volatile("cp.async.cg.shared.global [%0], [%1], 16;" :: "r"(s), "l"(gmem));
}
__device__ __forceinline__ void cp_commit() { asm volatile("cp.async.commit_group;"); }
__device__ __forceinline__ void cp_wait0()  { asm volatile("cp.async.wait_group 0;"); }
__device__ __forceinline__ void cp_wait1()  { asm volatile("cp.async.wait_group 1;"); }

__device__ __forceinline__ void ldsm_x4(unsigned& r0, unsigned& r1,
                                        unsigned& r2, unsigned& r3, const void* p) {
    unsigned s = (unsigned)__cvta_generic_to_shared(p);
    asm volatile("ldmatrix.sync.aligned.m8n8.x4.shared.b16 {%0,%1,%2,%3}, [%4];"
                 : "=r"(r0), "=r"(r1), "=r"(r2), "=r"(r3) : "r"(s));
}
__device__ __forceinline__ void ldsm_x4_trans(unsigned& r0, unsigned& r1,
                                              unsigned& r2, unsigned& r3, const void* p) {
    unsigned s = (unsigned)__cvta_generic_to_shared(p);
    asm volatile("ldmatrix.sync.aligned.m8n8.x4.trans.shared.b16 {%0,%1,%2,%3}, [%4];"
                 : "=r"(r0), "=r"(r1), "=r"(r2), "=r"(r3) : "r"(s));
}

// ---------------------------------------------------------------------------
// prep kernels
// ---------------------------------------------------------------------------
__global__ void to_half_kernel(const float* __restrict__ in, __half* __restrict__ out)
{
    const int i = (blockIdx.x * blockDim.x + threadIdx.x) * 4;
    float4 v = *(const float4*)(in + i);
    *(__half2*)&out[i]     = __floats2half2_rn(v.x, v.y);
    *(__half2*)&out[i + 2] = __floats2half2_rn(v.z, v.w);
}

// in f32 [K][N] -> out fp16 [N][K]
__global__ void transpose_to_half(const float* __restrict__ in, __half* __restrict__ out,
                                  int K, int N)
{
    __shared__ float tile[32][33];
    const int n0 = blockIdx.x * 32;
    const int k0 = blockIdx.y * 32;
    const int tx = threadIdx.x;
    const int ty = threadIdx.y;
#pragma unroll
    for (int j = 0; j < 4; j++)
        tile[ty + 8 * j][tx] = in[(size_t)(k0 + ty + 8 * j) * N + n0 + tx];
    __syncthreads();
#pragma unroll
    for (int j = 0; j < 4; j++)
        out[(size_t)(n0 + ty + 8 * j) * K + k0 + tx] = __float2half(tile[tx][ty + 8 * j]);
}

// ---------------------------------------------------------------------------
// fp16 GEMM: C[M,N](f32) = A[M,K](fp16 row-major) @ Bt[N,K](fp16) (+bias)
// Block 128x128, BK=64, 256 threads = 8 warps (2m x 4n), warp tile 64x32.
// 3-stage cp.async pipeline; fragments via ldmatrix.x4. Pitch 72 halfs.
// ---------------------------------------------------------------------------
#define GP 72
#define GEMM_SMEM (3 * 2 * 128 * GP * 2)   // 3 stages x (A + B), bytes

__global__ void __launch_bounds__(256, 2)
gemm_fp16(const __half* __restrict__ A, const __half* __restrict__ Bt,
          const float* __restrict__ bias, float* __restrict__ C,
          int M, int N, int K)
{
    extern __shared__ __half sh[];
    __half* Asm = sh;                    // [3][128][GP]
    __half* Bsm = sh + 3 * 128 * GP;     // [3][128][GP]

    const int bm = blockIdx.y * 128;
    const int bn = blockIdx.x * 128;
    const int tid = threadIdx.x;
    const int lane = tid & 31;
    const int w = tid >> 5;
    const int lrow = lane >> 2;
    const int lk = lane & 3;
    const int wm = (w & 1) * 64;
    const int wn = (w >> 1) * 32;

    // ldmatrix per-lane offsets
    const int a_row_off = lane & 15;             // A/x4: rows 0..15
    const int a_col_off = (lane >> 4) * 8;       // k half
    const int b_row_off = (lane >> 4) * 8 + (lane & 7);  // B pair: rows
    const int b_col_off = ((lane >> 3) & 1) * 8;         // k half

    const int srow = tid >> 1;              // 0..127
    const int sbase = (tid & 1) * 32;       // 0 or 32 (halfs)

    const __half* Aptr = A + (size_t)(bm + srow) * K + sbase;
    const __half* Bptr = Bt + (size_t)(bn + srow) * K + sbase;
    __half* Adst = Asm + srow * GP + sbase;
    __half* Bdst = Bsm + srow * GP + sbase;

    float acc[4][4][4];
#pragma unroll
    for (int mt = 0; mt < 4; mt++)
#pragma unroll
        for (int nt = 0; nt < 4; nt++)
#pragma unroll
            for (int i = 0; i < 4; i++) acc[mt][nt][i] = 0.0f;

    const int ntiles = K / 64;
    // prologue: stage tiles 0 and 1
#pragma unroll
    for (int i = 0; i < 4; i++) cp16(Adst + i * 8, Aptr + i * 8);
#pragma unroll
    for (int i = 0; i < 4; i++) cp16(Bdst + i * 8, Bptr + i * 8);
    cp_commit();
    if (ntiles > 1) {
        const int so = 128 * GP;
#pragma unroll
        for (int i = 0; i < 4; i++) cp16(Adst + so + i * 8, Aptr + 64 + i * 8);
#pragma unroll
        for (int i = 0; i < 4; i++) cp16(Bdst + so + i * 8, Bptr + 64 + i * 8);
        cp_commit();
    }

    for (int t = 0; t < ntiles; t++) {
        if (t + 1 < ntiles) cp_wait1(); else cp_wait0();
        __syncthreads();

        if (t + 2 < ntiles) {
            const int kn = (t + 2) * 64;
            const int so = ((t + 2) % 3) * 128 * GP;
#pragma unroll
            for (int i = 0; i < 4; i++) cp16(Adst + so + i * 8, Aptr + kn + i * 8);
#pragma unroll
            for (int i = 0; i < 4; i++) cp16(Bdst + so + i * 8, Bptr + kn + i * 8);
            cp_commit();
        }

        const __half* Ah = Asm + (t % 3) * 128 * GP;
        const __half* Bh = Bsm + (t % 3) * 128 * GP;
#pragma unroll
        for (int kc = 0; kc < 4; kc++) {
            const int kh = kc * 16;
            unsigned af[4][4];
#pragma unroll
            for (int mt = 0; mt < 4; mt++)
                ldsm_x4(af[mt][0], af[mt][1], af[mt][2], af[mt][3],
                        &Ah[(wm + mt * 16 + a_row_off) * GP + kh + a_col_off]);
            unsigned bf[4][2];
#pragma unroll
            for (int ntp = 0; ntp < 2; ntp++) {
                unsigned r0, r1, r2, r3;
                ldsm_x4(r0, r1, r2, r3,
                        &Bh[(wn + ntp * 16 + b_row_off) * GP + kh + b_col_off]);
                bf[2 * ntp][0] = r0;     bf[2 * ntp][1] = r1;
                bf[2 * ntp + 1][0] = r2; bf[2 * ntp + 1][1] = r3;
            }
#pragma unroll
            for (int nt = 0; nt < 4; nt++)
#pragma unroll
                for (int mt = 0; mt < 4; mt++)
                    mma_f16(acc[mt][nt], af[mt][0], af[mt][1], af[mt][2], af[mt][3],
                            bf[nt][0], bf[nt][1]);
        }
        __syncthreads();
    }

#pragma unroll
    for (int mt = 0; mt < 4; mt++) {
        const int row0 = bm + wm + mt * 16 + lrow;
#pragma unroll
        for (int nt = 0; nt < 4; nt++) {
            const int col = bn + wn + nt * 8 + lk * 2;
            float bx = 0.f, by = 0.f;
            if (bias) { bx = bias[col]; by = bias[col + 1]; }
            *(float2*)&C[(size_t)row0 * N + col] =
                make_float2(acc[mt][nt][0] + bx, acc[mt][nt][1] + by);
            *(float2*)&C[(size_t)(row0 + 8) * N + col] =
                make_float2(acc[mt][nt][2] + bx, acc[mt][nt][3] + by);
        }
    }
}

// ---------------------------------------------------------------------------
// RoPE + split + transpose -> fp16. q pre-scaled by 1/8.
// ---------------------------------------------------------------------------
__global__ void rope_split_kernel()
{
    const int idx = blockIdx.x * blockDim.x + threadIdx.x;
    const int d2 = idx & 31;
    const int t  = (idx >> 5) & (T_ - 1);
    const int bh = idx >> 16;
    const int h = bh & (H_ - 1);
    const int b = bh >> 4;

    const float* row = g_qkv + ((size_t)(b * T_ + t)) * (3 * D_) + h * DH_;
    const float q0 = row[d2];
    const float q1 = row[d2 + 32];
    const float k0 = row[D_ + d2];
    const float k1 = row[D_ + d2 + 32];
    const float v0 = row[2 * D_ + d2];
    const float v1 = row[2 * D_ + d2 + 32];

    const float inv = 1.0f / powf(10000.0f, (float)d2 * (1.0f / 32.0f));
    const float ang = (float)t * inv;
    float sn, cs;
    sincosf(ang, &sn, &cs);

    const size_t obase = ((size_t)bh * T_ + t) * DH_;
    g_qh[obase + d2]      = __float2half((q0 * cs - q1 * sn) * 0.125f);
    g_qh[obase + d2 + 32] = __float2half((q1 * cs + q0 * sn) * 0.125f);
    g_kh[obase + d2]      = __float2half(k0 * cs - k1 * sn);
    g_kh[obase + d2 + 32] = __float2half(k1 * cs + k0 * sn);
    g_vh[obase + d2]      = __float2half(v0);
    g_vh[obase + d2 + 32] = __float2half(v1);
}

// ---------------------------------------------------------------------------
// fp16 tensor-core flash attention, double-buffered K/V, ldmatrix frags.
// Block = (128-row q tile, bh), 4 warps, 32 q rows/warp (2 m16 groups).
// smem: qs[128][72] + 2 x (ks[64][72] + vs[64][72]) = 54KB -> 3 blocks/SM.
// ---------------------------------------------------------------------------
#define AP 72
#define ATTN_SMEM ((128 * AP + 4 * 64 * AP) * 2)

__global__ void __launch_bounds__(128, 3)
attn_fp16_kernel()
{
    extern __shared__ __half sh[];
    __half* qs = sh;                         // [128][72]
    __half* kbuf[2] = { sh + 128 * AP, sh + 128 * AP + 2 * 64 * AP };
    __half* vbuf[2] = { sh + 128 * AP + 64 * AP, sh + 128 * AP + 3 * 64 * AP };

    const int qt = (T_ / 128 - 1) - blockIdx.x;   // heavy blocks first
    const int bh = blockIdx.y;
    const int tid = threadIdx.x;
    const int lane = tid & 31;
    const int w = tid >> 5;
    const int lrow = lane >> 2;
    const int lk = lane & 3;
    const int wrow = w * 32;

    const int a_row_off = lane & 15;
    const int a_col_off = (lane >> 4) * 8;
    const int b_row_off = (lane >> 4) * 8 + (lane & 7);
    const int b_col_off = ((lane >> 3) & 1) * 8;

    const __half* Qb = g_qh + ((size_t)bh * T_ + qt * 128) * DH_;
    const __half* Kb = g_kh + (size_t)bh * T_ * DH_;
    const __half* Vb = g_vh + (size_t)bh * T_ * DH_;

    // prologue: stage Q + K0/V0 in one group
#pragma unroll
    for (int i = 0; i < 8; i++) {
        const int e = tid + i * 128;      // 0..1023
        const int r = e >> 3;
        const int c = (e & 7) * 8;
        cp16(&qs[r * AP + c], &Qb[r * 64 + c]);
    }
#pragma unroll
    for (int i = 0; i < 4; i++) {
        const int e = tid + i * 128;      // 0..511
        const int r = e >> 3;
        const int c = (e & 7) * 8;
        cp16(&kbuf[0][r * AP + c], Kb + (size_t)r * 64 + c);
        cp16(&vbuf[0][r * AP + c], Vb + (size_t)r * 64 + c);
    }
    cp_commit();

    float m[2][2], l[2][2];
    float oacc[2][8][4];
#pragma unroll
    for (int mg = 0; mg < 2; mg++) {
        m[mg][0] = -1e30f; m[mg][1] = -1e30f;
        l[mg][0] = 0.f;    l[mg][1] = 0.f;
#pragma unroll
        for (int nt = 0; nt < 8; nt++)
#pragma unroll
            for (int i = 0; i < 4; i++) oacc[mg][nt][i] = 0.f;
    }

    const int ktmax = 2 * qt + 1;
    for (int kt = 0; kt <= ktmax; kt++) {
        const int s = kt & 1;
        cp_wait0();
        __syncthreads();

        if (kt < ktmax) {
#pragma unroll
            for (int i = 0; i < 4; i++) {
                const int e = tid + i * 128;
                const int r = e >> 3;
                const int c = (e & 7) * 8;
                cp16(&kbuf[s ^ 1][r * AP + c], Kb + (size_t)((kt + 1) * 64 + r) * 64 + c);
                cp16(&vbuf[s ^ 1][r * AP + c], Vb + (size_t)((kt + 1) * 64 + r) * 64 + c);
            }
            cp_commit();
        }

        const __half* ks = kbuf[s];
        const __half* vs = vbuf[s];

        // ---- S = Q @ K^T : warp computes 32 x 64 ----
        float sacc[2][8][4];
#pragma unroll
        for (int mg = 0; mg < 2; mg++)
#pragma unroll
            for (int nt = 0; nt < 8; nt++)
#pragma unroll
                for (int i = 0; i < 4; i++) sacc[mg][nt][i] = 0.f;

#pragma unroll
        for (int kc = 0; kc < 4; kc++) {
            const int kh = kc * 16;
            unsigned af[2][4];
#pragma unroll
            for (int mg = 0; mg < 2; mg++)
                ldsm_x4(af[mg][0], af[mg][1], af[mg][2], af[mg][3],
                        &qs[(wrow + mg * 16 + a_row_off) * AP + kh + a_col_off]);
            unsigned bf[8][2];
#pragma unroll
            for (int ntp = 0; ntp < 4; ntp++) {
                unsigned r0, r1, r2, r3;
                ldsm_x4(r0, r1, r2, r3,
                        &ks[(ntp * 16 + b_row_off) * AP + kh + b_col_off]);
                bf[2 * ntp][0] = r0;     bf[2 * ntp][1] = r1;
                bf[2 * ntp + 1][0] = r2; bf[2 * ntp + 1][1] = r3;
            }
#pragma unroll
            for (int nt = 0; nt < 8; nt++)
#pragma unroll
                for (int mg = 0; mg < 2; mg++)
                    mma_f16(sacc[mg][nt], af[mg][0], af[mg][1], af[mg][2], af[mg][3],
                            bf[nt][0], bf[nt][1]);
        }

        // ---- causal mask (near-diagonal tiles only) ----
        if (kt * 64 + 63 > qt * 128 + wrow) {
#pragma unroll
            for (int mg = 0; mg < 2; mg++) {
                const int rg0 = qt * 128 + wrow + mg * 16 + lrow;
                const int rg1 = rg0 + 8;
#pragma unroll
                for (int nt = 0; nt < 8; nt++) {
                    const int cg = kt * 64 + nt * 8 + lk * 2;
                    if (cg > rg0)     sacc[mg][nt][0] = -1e30f;
                    if (cg + 1 > rg0) sacc[mg][nt][1] = -1e30f;
                    if (cg > rg1)     sacc[mg][nt][2] = -1e30f;
                    if (cg + 1 > rg1) sacc[mg][nt][3] = -1e30f;
                }
            }
        }

        // ---- online softmax; pack P to half2 A-frags ----
        unsigned pk01[2][8], pk23[2][8];
#pragma unroll
        for (int mg = 0; mg < 2; mg++) {
            float tm0 = -1e30f, tm1 = -1e30f;
#pragma unroll
            for (int nt = 0; nt < 8; nt++) {
                tm0 = fmaxf(tm0, fmaxf(sacc[mg][nt][0], sacc[mg][nt][1]));
                tm1 = fmaxf(tm1, fmaxf(sacc[mg][nt][2], sacc[mg][nt][3]));
            }
            tm0 = fmaxf(tm0, __shfl_xor_sync(0xffffffffu, tm0, 1));
            tm0 = fmaxf(tm0, __shfl_xor_sync(0xffffffffu, tm0, 2));
            tm1 = fmaxf(tm1, __shfl_xor_sync(0xffffffffu, tm1, 1));
            tm1 = fmaxf(tm1, __shfl_xor_sync(0xffffffffu, tm1, 2));

            const float mn0 = fmaxf(m[mg][0], tm0);
            const float mn1 = fmaxf(m[mg][1], tm1);
            const float corr0 = __expf(m[mg][0] - mn0);
            const float corr1 = __expf(m[mg][1] - mn1);
            m[mg][0] = mn0; m[mg][1] = mn1;

            float sum0 = 0.f, sum1 = 0.f;
#pragma unroll
            for (int nt = 0; nt < 8; nt++) {
                const float p00 = __expf(sacc[mg][nt][0] - mn0);
                const float p01 = __expf(sacc[mg][nt][1] - mn0);
                const float p10 = __expf(sacc[mg][nt][2] - mn1);
                const float p11 = __expf(sacc[mg][nt][3] - mn1);
                sum0 += p00 + p01;
                sum1 += p10 + p11;
                pk01[mg][nt] = pack_h2(p00, p01);
                pk23[mg][nt] = pack_h2(p10, p11);
            }
            sum0 += __shfl_xor_sync(0xffffffffu, sum0, 1);
            sum0 += __shfl_xor_sync(0xffffffffu, sum0, 2);
            sum1 += __shfl_xor_sync(0xffffffffu, sum1, 1);
            sum1 += __shfl_xor_sync(0xffffffffu, sum1, 2);
            l[mg][0] = l[mg][0] * corr0 + sum0;
            l[mg][1] = l[mg][1] * corr1 + sum1;

#pragma unroll
            for (int nt = 0; nt < 8; nt++) {
                oacc[mg][nt][0] *= corr0;
                oacc[mg][nt][1] *= corr0;
                oacc[mg][nt][2] *= corr1;
                oacc[mg][nt][3] *= corr1;
            }
        }

        // ---- O += P @ V : V B-frags via ldmatrix.trans ----
#pragma unroll
        for (int kc = 0; kc < 4; kc++) {
            const int g = lane >> 3;
            const int li = lane & 7;
            const int vrow = kc * 16 + (g & 1) * 8 + li;
#pragma unroll
            for (int ntp = 0; ntp < 4; ntp++) {
                const int vcol = ntp * 16 + (g >> 1) * 8;
                unsigned r0, r1, r2, r3;
                ldsm_x4_trans(r0, r1, r2, r3, &vs[vrow * AP + vcol]);
#pragma unroll
                for (int mg = 0; mg < 2; mg++) {
                    mma_f16(oacc[mg][ntp * 2],
                            pk01[mg][2 * kc], pk23[mg][2 * kc],
                            pk01[mg][2 * kc + 1], pk23[mg][2 * kc + 1], r0, r1);
                    mma_f16(oacc[mg][ntp * 2 + 1],
                            pk01[mg][2 * kc], pk23[mg][2 * kc],
                            pk01[mg][2 * kc + 1], pk23[mg][2 * kc + 1], r2, r3);
                }
            }
        }
    }

    // ---- epilogue -> fp16 g_attnh ----
    const int b = bh >> 4;
    const int h = bh & (H_ - 1);
#pragma unroll
    for (int mg = 0; mg < 2; mg++) {
        const float il0 = 1.0f / l[mg][0];
        const float il1 = 1.0f / l[mg][1];
        const int t0 = qt * 128 + wrow + mg * 16 + lrow;
        const int t1 = t0 + 8;
        const size_t base0 = ((size_t)(b * T_ + t0)) * D_ + h * DH_;
        const size_t base1 = ((size_t)(b * T_ + t1)) * D_ + h * DH_;
#pragma unroll
        for (int nt = 0; nt < 8; nt++) {
            const int c0 = nt * 8 + lk * 2;
            *(__half2*)&g_attnh[base0 + c0] =
                __floats2half2_rn(oacc[mg][nt][0] * il0, oacc[mg][nt][1] * il0);
            *(__half2*)&g_attnh[base1 + c0] =
                __floats2half2_rn(oacc[mg][nt][2] * il1, oacc[mg][nt][3] * il1);
        }
    }
}

// ---------------------------------------------------------------------------
// kernel_launch
// ---------------------------------------------------------------------------
extern "C" void kernel_launch(void* const* d_in, const int* in_sizes, int n_in,
                              void* d_out, int out_size)
{
    (void)in_sizes; (void)n_in; (void)out_size;
    const float* x     = (const float*)d_in[0];
    const float* qkv_w = (const float*)d_in[2];
    const float* out_w = (const float*)d_in[3];
    const float* out_b = (const float*)d_in[4];
    float* out = (float*)d_out;

    void *p_xh, *p_w1t, *p_w2t, *p_qkv, *p_attnh;
    cudaGetSymbolAddress(&p_xh, g_xh);
    cudaGetSymbolAddress(&p_w1t, g_w1t);
    cudaGetSymbolAddress(&p_w2t, g_w2t);
    cudaGetSymbolAddress(&p_qkv, g_qkv);
    cudaGetSymbolAddress(&p_attnh, g_attnh);

    cudaFuncSetAttribute(gemm_fp16,
                         cudaFuncAttributeMaxDynamicSharedMemorySize, GEMM_SMEM);
    cudaFuncSetAttribute(attn_fp16_kernel,
                         cudaFuncAttributeMaxDynamicSharedMemorySize, ATTN_SMEM);

    // 0) prep: x -> fp16, weights -> fp16 transposed [N][K]
    to_half_kernel<<<(NROW * D_) / 1024, 256>>>(x, (__half*)p_xh);
    transpose_to_half<<<dim3(3 * D_ / 32, D_ / 32), dim3(32, 8)>>>(
        qkv_w, (__half*)p_w1t, D_, 3 * D_);
    transpose_to_half<<<dim3(D_ / 32, D_ / 32), dim3(32, 8)>>>(
        out_w, (__half*)p_w2t, D_, D_);

    // 1) QKV projection (fp16 tensor cores)
    gemm_fp16<<<dim3((3 * D_) / 128, NROW / 128), 256, GEMM_SMEM>>>(
        (const __half*)p_xh, (const __half*)p_w1t, nullptr, (float*)p_qkv,
        NROW, 3 * D_, D_);

    // 2) RoPE + split/transpose -> fp16
    rope_split_kernel<<<(BH_ * T_ * 32) / 256, 256>>>();

    // 3) causal flash attention (fp16 tensor cores)
    attn_fp16_kernel<<<dim3(T_ / 128, BH_), 128, ATTN_SMEM>>>();

    // 4) output projection + bias
    gemm_fp16<<<dim3(D_ / 128, NROW / 128), 256, GEMM_SMEM>>>(
        (const __half*)p_attnh, (const __half*)p_w2t, out_b, out, NROW, D_, D_);
}

// round 11
// speedup vs baseline: 2.4142x; 1.1703x over previous
#include <cuda_runtime.h>
#include <cuda_fp16.h>
#include <math.h>

// Problem constants
#define B_ 2
#define T_ 2048
#define D_ 1024
#define H_ 16
#define DH_ 64
#define NROW (B_ * T_)        // 4096
#define BH_ (B_ * H_)         // 32

// ---------------------------------------------------------------------------
// Scratch
// ---------------------------------------------------------------------------
__device__ __half g_xh [(size_t)NROW * D_];             // fp16 x
__device__ __half g_w1t[(size_t)(3 * D_) * D_];         // fp16 qkv_w transposed [N][K]
__device__ __half g_w2t[(size_t)D_ * D_];               // fp16 out_w transposed [N][K]
__device__ float  g_qkv[(size_t)NROW * 3 * D_];         // [4096, 3072] f32
__device__ __half g_qh[(size_t)BH_ * T_ * DH_];
__device__ __half g_kh[(size_t)BH_ * T_ * DH_];
__device__ __half g_vh[(size_t)BH_ * T_ * DH_];
__device__ __half g_attnh[(size_t)NROW * D_];           // [4096, 1024] fp16

// ---------------------------------------------------------------------------
// helpers
// ---------------------------------------------------------------------------
__device__ __forceinline__ unsigned pack_h2(float a, float b) {
    __half2 h = __floats2half2_rn(a, b);
    return *(unsigned*)&h;
}
__device__ __forceinline__ void mma_f16(float* c,
                                        unsigned a0, unsigned a1, unsigned a2, unsigned a3,
                                        unsigned b0, unsigned b1) {
    asm volatile("mma.sync.aligned.m16n8k16.row.col.f32.f16.f16.f32 "
                 "{%0,%1,%2,%3}, {%4,%5,%6,%7}, {%8,%9}, {%0,%1,%2,%3};"
                 : "+f"(c[0]), "+f"(c[1]), "+f"(c[2]), "+f"(c[3])
                 : "r"(a0), "r"(a1), "r"(a2), "r"(a3), "r"(b0), "r"(b1));
}
__device__ __forceinline__ void cp16(void* smem, const void* gmem) {
    unsigned s = (unsigned)__cvta_generic_to_shared(smem);
    asm volatile("cp.async.cg.shared.global [%0], [%1], 16;" :: "r"(s), "l"(gmem));
}
__device__ __forceinline__ void cp_commit() { asm volatile("cp.async.commit_group;"); }
__device__ __forceinline__ void cp_wait0()  { asm volatile("cp.async.wait_group 0;"); }

__device__ __forceinline__ void ldsm_x4(unsigned& r0, unsigned& r1,
                                        unsigned& r2, unsigned& r3, const void* p) {
    unsigned s = (unsigned)__cvta_generic_to_shared(p);
    asm volatile("ldmatrix.sync.aligned.m8n8.x4.shared.b16 {%0,%1,%2,%3}, [%4];"
                 : "=r"(r0), "=r"(r1), "=r"(r2), "=r"(r3) : "r"(s));
}
__device__ __forceinline__ void ldsm_x4_trans(unsigned& r0, unsigned& r1,
                                              unsigned& r2, unsigned& r3, const void* p) {
    unsigned s = (unsigned)__cvta_generic_to_shared(p);
    asm volatile("ldmatrix.sync.aligned.m8n8.x4.trans.shared.b16 {%0,%1,%2,%3}, [%4];"
                 : "=r"(r0), "=r"(r1), "=r"(r2), "=r"(r3) : "r"(s));
}

// ---------------------------------------------------------------------------
// prep kernels
// ---------------------------------------------------------------------------
__global__ void to_half_kernel(const float* __restrict__ in, __half* __restrict__ out)
{
    const int i = (blockIdx.x * blockDim.x + threadIdx.x) * 4;
    float4 v = *(const float4*)(in + i);
    *(__half2*)&out[i]     = __floats2half2_rn(v.x, v.y);
    *(__half2*)&out[i + 2] = __floats2half2_rn(v.z, v.w);
}

// in f32 [K][N] -> out fp16 [N][K]
__global__ void transpose_to_half(const float* __restrict__ in, __half* __restrict__ out,
                                  int K, int N)
{
    __shared__ float tile[32][33];
    const int n0 = blockIdx.x * 32;
    const int k0 = blockIdx.y * 32;
    const int tx = threadIdx.x;
    const int ty = threadIdx.y;
#pragma unroll
    for (int j = 0; j < 4; j++)
        tile[ty + 8 * j][tx] = in[(size_t)(k0 + ty + 8 * j) * N + n0 + tx];
    __syncthreads();
#pragma unroll
    for (int j = 0; j < 4; j++)
        out[(size_t)(n0 + ty + 8 * j) * K + k0 + tx] = __float2half(tile[tx][ty + 8 * j]);
}

// ---------------------------------------------------------------------------
// fp16 GEMM v2: C[M,N](f32) = A[M,K](fp16 row-major) @ Bt[N,K](fp16) (+bias)
// Block tile 128(M) x 256(N), BK=64, 256 threads = 8 warps (2m x 4n),
// warp tile 64x64 (4/1 HMMA:LDSM feed ratio). 2-stage cp.async.
// smem: 2 x (128+256) x 72 halfs = 108KB -> 1 CTA/SM.
// Staging: 16B chunk e -> row e>>3, col (e&7)*8 halfs. A=1024 chunks (4/thr),
// B=2048 chunks (8/thr).
// ---------------------------------------------------------------------------
#define GP 72
#define GEMM_SMEM (2 * (128 + 256) * GP * 2)

__global__ void __launch_bounds__(256, 1)
gemm_fp16(const __half* __restrict__ A, const __half* __restrict__ Bt,
          const float* __restrict__ bias, float* __restrict__ C,
          int M, int N, int K)
{
    extern __shared__ __half sh[];
    __half* Asm = sh;                    // [2][128][GP]
    __half* Bsm = sh + 2 * 128 * GP;     // [2][256][GP]

    const int bm = blockIdx.y * 128;
    const int bn = blockIdx.x * 256;
    const int tid = threadIdx.x;
    const int lane = tid & 31;
    const int w = tid >> 5;
    const int lrow = lane >> 2;
    const int lk = lane & 3;
    const int wm = (w & 1) * 64;
    const int wn = (w >> 1) * 64;

    // ldmatrix per-lane offsets
    const int a_row_off = lane & 15;
    const int a_col_off = (lane >> 4) * 8;
    const int b_row_off = (lane >> 4) * 8 + (lane & 7);
    const int b_col_off = ((lane >> 3) & 1) * 8;

    float acc[4][8][4];
#pragma unroll
    for (int mt = 0; mt < 4; mt++)
#pragma unroll
        for (int nt = 0; nt < 8; nt++)
#pragma unroll
            for (int i = 0; i < 4; i++) acc[mt][nt][i] = 0.0f;

    const int ntiles = K / 64;

    // prologue: stage tile 0 into buffer 0
    {
#pragma unroll
        for (int i = 0; i < 4; i++) {
            const int e = tid + i * 256;        // 0..1023
            const int r = e >> 3;
            const int c = (e & 7) * 8;
            cp16(&Asm[r * GP + c], A + (size_t)(bm + r) * K + c);
        }
#pragma unroll
        for (int i = 0; i < 8; i++) {
            const int e = tid + i * 256;        // 0..2047
            const int r = e >> 3;
            const int c = (e & 7) * 8;
            cp16(&Bsm[r * GP + c], Bt + (size_t)(bn + r) * K + c);
        }
        cp_commit();
    }

    for (int t = 0; t < ntiles; t++) {
        const int s = t & 1;
        cp_wait0();
        __syncthreads();

        if (t + 1 < ntiles) {
            const int kn = (t + 1) * 64;
            __half* Ad = Asm + (s ^ 1) * 128 * GP;
            __half* Bd = Bsm + (s ^ 1) * 256 * GP;
#pragma unroll
            for (int i = 0; i < 4; i++) {
                const int e = tid + i * 256;
                const int r = e >> 3;
                const int c = (e & 7) * 8;
                cp16(&Ad[r * GP + c], A + (size_t)(bm + r) * K + kn + c);
            }
#pragma unroll
            for (int i = 0; i < 8; i++) {
                const int e = tid + i * 256;
                const int r = e >> 3;
                const int c = (e & 7) * 8;
                cp16(&Bd[r * GP + c], Bt + (size_t)(bn + r) * K + kn + c);
            }
            cp_commit();
        }

        const __half* Ah = Asm + s * 128 * GP;
        const __half* Bh = Bsm + s * 256 * GP;
#pragma unroll
        for (int kc = 0; kc < 4; kc++) {
            const int kh = kc * 16;
            unsigned af[4][4];
#pragma unroll
            for (int mt = 0; mt < 4; mt++)
                ldsm_x4(af[mt][0], af[mt][1], af[mt][2], af[mt][3],
                        &Ah[(wm + mt * 16 + a_row_off) * GP + kh + a_col_off]);
            unsigned bf[8][2];
#pragma unroll
            for (int ntp = 0; ntp < 4; ntp++) {
                unsigned r0, r1, r2, r3;
                ldsm_x4(r0, r1, r2, r3,
                        &Bh[(wn + ntp * 16 + b_row_off) * GP + kh + b_col_off]);
                bf[2 * ntp][0] = r0;     bf[2 * ntp][1] = r1;
                bf[2 * ntp + 1][0] = r2; bf[2 * ntp + 1][1] = r3;
            }
#pragma unroll
            for (int nt = 0; nt < 8; nt++)
#pragma unroll
                for (int mt = 0; mt < 4; mt++)
                    mma_f16(acc[mt][nt], af[mt][0], af[mt][1], af[mt][2], af[mt][3],
                            bf[nt][0], bf[nt][1]);
        }
        __syncthreads();
    }

#pragma unroll
    for (int mt = 0; mt < 4; mt++) {
        const int row0 = bm + wm + mt * 16 + lrow;
#pragma unroll
        for (int nt = 0; nt < 8; nt++) {
            const int col = bn + wn + nt * 8 + lk * 2;
            float bx = 0.f, by = 0.f;
            if (bias) { bx = bias[col]; by = bias[col + 1]; }
            *(float2*)&C[(size_t)row0 * N + col] =
                make_float2(acc[mt][nt][0] + bx, acc[mt][nt][1] + by);
            *(float2*)&C[(size_t)(row0 + 8) * N + col] =
                make_float2(acc[mt][nt][2] + bx, acc[mt][nt][3] + by);
        }
    }
}

// ---------------------------------------------------------------------------
// RoPE + split + transpose -> fp16. q pre-scaled by 1/8.
// ---------------------------------------------------------------------------
__global__ void rope_split_kernel()
{
    const int idx = blockIdx.x * blockDim.x + threadIdx.x;
    const int d2 = idx & 31;
    const int t  = (idx >> 5) & (T_ - 1);
    const int bh = idx >> 16;
    const int h = bh & (H_ - 1);
    const int b = bh >> 4;

    const float* row = g_qkv + ((size_t)(b * T_ + t)) * (3 * D_) + h * DH_;
    const float q0 = row[d2];
    const float q1 = row[d2 + 32];
    const float k0 = row[D_ + d2];
    const float k1 = row[D_ + d2 + 32];
    const float v0 = row[2 * D_ + d2];
    const float v1 = row[2 * D_ + d2 + 32];

    const float inv = 1.0f / powf(10000.0f, (float)d2 * (1.0f / 32.0f));
    const float ang = (float)t * inv;
    float sn, cs;
    sincosf(ang, &sn, &cs);

    const size_t obase = ((size_t)bh * T_ + t) * DH_;
    g_qh[obase + d2]      = __float2half((q0 * cs - q1 * sn) * 0.125f);
    g_qh[obase + d2 + 32] = __float2half((q1 * cs + q0 * sn) * 0.125f);
    g_kh[obase + d2]      = __float2half(k0 * cs - k1 * sn);
    g_kh[obase + d2 + 32] = __float2half(k1 * cs + k0 * sn);
    g_vh[obase + d2]      = __float2half(v0);
    g_vh[obase + d2 + 32] = __float2half(v1);
}

// ---------------------------------------------------------------------------
// fp16 tensor-core flash attention (R8 best, unchanged).
// ---------------------------------------------------------------------------
#define AP 72
#define ATTN_SMEM ((128 * AP + 4 * 64 * AP) * 2)

__global__ void __launch_bounds__(128, 3)
attn_fp16_kernel()
{
    extern __shared__ __half sh[];
    __half* qs = sh;                         // [128][72]
    __half* kbuf[2] = { sh + 128 * AP, sh + 128 * AP + 2 * 64 * AP };
    __half* vbuf[2] = { sh + 128 * AP + 64 * AP, sh + 128 * AP + 3 * 64 * AP };

    const int qt = (T_ / 128 - 1) - blockIdx.x;   // heavy blocks first
    const int bh = blockIdx.y;
    const int tid = threadIdx.x;
    const int lane = tid & 31;
    const int w = tid >> 5;
    const int lrow = lane >> 2;
    const int lk = lane & 3;
    const int wrow = w * 32;

    const int a_row_off = lane & 15;
    const int a_col_off = (lane >> 4) * 8;
    const int b_row_off = (lane >> 4) * 8 + (lane & 7);
    const int b_col_off = ((lane >> 3) & 1) * 8;

    const __half* Qb = g_qh + ((size_t)bh * T_ + qt * 128) * DH_;
    const __half* Kb = g_kh + (size_t)bh * T_ * DH_;
    const __half* Vb = g_vh + (size_t)bh * T_ * DH_;

#pragma unroll
    for (int i = 0; i < 8; i++) {
        const int e = tid + i * 128;
        const int r = e >> 3;
        const int c = (e & 7) * 8;
        cp16(&qs[r * AP + c], &Qb[r * 64 + c]);
    }
#pragma unroll
    for (int i = 0; i < 4; i++) {
        const int e = tid + i * 128;
        const int r = e >> 3;
        const int c = (e & 7) * 8;
        cp16(&kbuf[0][r * AP + c], Kb + (size_t)r * 64 + c);
        cp16(&vbuf[0][r * AP + c], Vb + (size_t)r * 64 + c);
    }
    cp_commit();

    float m[2][2], l[2][2];
    float oacc[2][8][4];
#pragma unroll
    for (int mg = 0; mg < 2; mg++) {
        m[mg][0] = -1e30f; m[mg][1] = -1e30f;
        l[mg][0] = 0.f;    l[mg][1] = 0.f;
#pragma unroll
        for (int nt = 0; nt < 8; nt++)
#pragma unroll
            for (int i = 0; i < 4; i++) oacc[mg][nt][i] = 0.f;
    }

    const int ktmax = 2 * qt + 1;
    for (int kt = 0; kt <= ktmax; kt++) {
        const int s = kt & 1;
        cp_wait0();
        __syncthreads();

        if (kt < ktmax) {
#pragma unroll
            for (int i = 0; i < 4; i++) {
                const int e = tid + i * 128;
                const int r = e >> 3;
                const int c = (e & 7) * 8;
                cp16(&kbuf[s ^ 1][r * AP + c], Kb + (size_t)((kt + 1) * 64 + r) * 64 + c);
                cp16(&vbuf[s ^ 1][r * AP + c], Vb + (size_t)((kt + 1) * 64 + r) * 64 + c);
            }
            cp_commit();
        }

        const __half* ks = kbuf[s];
        const __half* vs = vbuf[s];

        float sacc[2][8][4];
#pragma unroll
        for (int mg = 0; mg < 2; mg++)
#pragma unroll
            for (int nt = 0; nt < 8; nt++)
#pragma unroll
                for (int i = 0; i < 4; i++) sacc[mg][nt][i] = 0.f;

#pragma unroll
        for (int kc = 0; kc < 4; kc++) {
            const int kh = kc * 16;
            unsigned af[2][4];
#pragma unroll
            for (int mg = 0; mg < 2; mg++)
                ldsm_x4(af[mg][0], af[mg][1], af[mg][2], af[mg][3],
                        &qs[(wrow + mg * 16 + a_row_off) * AP + kh + a_col_off]);
            unsigned bf[8][2];
#pragma unroll
            for (int ntp = 0; ntp < 4; ntp++) {
                unsigned r0, r1, r2, r3;
                ldsm_x4(r0, r1, r2, r3,
                        &ks[(ntp * 16 + b_row_off) * AP + kh + b_col_off]);
                bf[2 * ntp][0] = r0;     bf[2 * ntp][1] = r1;
                bf[2 * ntp + 1][0] = r2; bf[2 * ntp + 1][1] = r3;
            }
#pragma unroll
            for (int nt = 0; nt < 8; nt++)
#pragma unroll
                for (int mg = 0; mg < 2; mg++)
                    mma_f16(sacc[mg][nt], af[mg][0], af[mg][1], af[mg][2], af[mg][3],
                            bf[nt][0], bf[nt][1]);
        }

        if (kt * 64 + 63 > qt * 128 + wrow) {
#pragma unroll
            for (int mg = 0; mg < 2; mg++) {
                const int rg0 = qt * 128 + wrow + mg * 16 + lrow;
                const int rg1 = rg0 + 8;
#pragma unroll
                for (int nt = 0; nt < 8; nt++) {
                    const int cg = kt * 64 + nt * 8 + lk * 2;
                    if (cg > rg0)     sacc[mg][nt][0] = -1e30f;
                    if (cg + 1 > rg0) sacc[mg][nt][1] = -1e30f;
                    if (cg > rg1)     sacc[mg][nt][2] = -1e30f;
                    if (cg + 1 > rg1) sacc[mg][nt][3] = -1e30f;
                }
            }
        }

        unsigned pk01[2][8], pk23[2][8];
#pragma unroll
        for (int mg = 0; mg < 2; mg++) {
            float tm0 = -1e30f, tm1 = -1e30f;
#pragma unroll
            for (int nt = 0; nt < 8; nt++) {
                tm0 = fmaxf(tm0, fmaxf(sacc[mg][nt][0], sacc[mg][nt][1]));
                tm1 = fmaxf(tm1, fmaxf(sacc[mg][nt][2], sacc[mg][nt][3]));
            }
            tm0 = fmaxf(tm0, __shfl_xor_sync(0xffffffffu, tm0, 1));
            tm0 = fmaxf(tm0, __shfl_xor_sync(0xffffffffu, tm0, 2));
            tm1 = fmaxf(tm1, __shfl_xor_sync(0xffffffffu, tm1, 1));
            tm1 = fmaxf(tm1, __shfl_xor_sync(0xffffffffu, tm1, 2));

            const float mn0 = fmaxf(m[mg][0], tm0);
            const float mn1 = fmaxf(m[mg][1], tm1);
            const float corr0 = __expf(m[mg][0] - mn0);
            const float corr1 = __expf(m[mg][1] - mn1);
            m[mg][0] = mn0; m[mg][1] = mn1;

            float sum0 = 0.f, sum1 = 0.f;
#pragma unroll
            for (int nt = 0; nt < 8; nt++) {
                const float p00 = __expf(sacc[mg][nt][0] - mn0);
                const float p01 = __expf(sacc[mg][nt][1] - mn0);
                const float p10 = __expf(sacc[mg][nt][2] - mn1);
                const float p11 = __expf(sacc[mg][nt][3] - mn1);
                sum0 += p00 + p01;
                sum1 += p10 + p11;
                pk01[mg][nt] = pack_h2(p00, p01);
                pk23[mg][nt] = pack_h2(p10, p11);
            }
            sum0 += __shfl_xor_sync(0xffffffffu, sum0, 1);
            sum0 += __shfl_xor_sync(0xffffffffu, sum0, 2);
            sum1 += __shfl_xor_sync(0xffffffffu, sum1, 1);
            sum1 += __shfl_xor_sync(0xffffffffu, sum1, 2);
            l[mg][0] = l[mg][0] * corr0 + sum0;
            l[mg][1] = l[mg][1] * corr1 + sum1;

#pragma unroll
            for (int nt = 0; nt < 8; nt++) {
                oacc[mg][nt][0] *= corr0;
                oacc[mg][nt][1] *= corr0;
                oacc[mg][nt][2] *= corr1;
                oacc[mg][nt][3] *= corr1;
            }
        }

#pragma unroll
        for (int kc = 0; kc < 4; kc++) {
            const int g = lane >> 3;
            const int li = lane & 7;
            const int vrow = kc * 16 + (g & 1) * 8 + li;
#pragma unroll
            for (int ntp = 0; ntp < 4; ntp++) {
                const int vcol = ntp * 16 + (g >> 1) * 8;
                unsigned r0, r1, r2, r3;
                ldsm_x4_trans(r0, r1, r2, r3, &vs[vrow * AP + vcol]);
#pragma unroll
                for (int mg = 0; mg < 2; mg++) {
                    mma_f16(oacc[mg][ntp * 2],
                            pk01[mg][2 * kc], pk23[mg][2 * kc],
                            pk01[mg][2 * kc + 1], pk23[mg][2 * kc + 1], r0, r1);
                    mma_f16(oacc[mg][ntp * 2 + 1],
                            pk01[mg][2 * kc], pk23[mg][2 * kc],
                            pk01[mg][2 * kc + 1], pk23[mg][2 * kc + 1], r2, r3);
                }
            }
        }
    }

    const int b = bh >> 4;
    const int h = bh & (H_ - 1);
#pragma unroll
    for (int mg = 0; mg < 2; mg++) {
        const float il0 = 1.0f / l[mg][0];
        const float il1 = 1.0f / l[mg][1];
        const int t0 = qt * 128 + wrow + mg * 16 + lrow;
        const int t1 = t0 + 8;
        const size_t base0 = ((size_t)(b * T_ + t0)) * D_ + h * DH_;
        const size_t base1 = ((size_t)(b * T_ + t1)) * D_ + h * DH_;
#pragma unroll
        for (int nt = 0; nt < 8; nt++) {
            const int c0 = nt * 8 + lk * 2;
            *(__half2*)&g_attnh[base0 + c0] =
                __floats2half2_rn(oacc[mg][nt][0] * il0, oacc[mg][nt][1] * il0);
            *(__half2*)&g_attnh[base1 + c0] =
                __floats2half2_rn(oacc[mg][nt][2] * il1, oacc[mg][nt][3] * il1);
        }
    }
}

// ---------------------------------------------------------------------------
// kernel_launch
// ---------------------------------------------------------------------------
extern "C" void kernel_launch(void* const* d_in, const int* in_sizes, int n_in,
                              void* d_out, int out_size)
{
    (void)in_sizes; (void)n_in; (void)out_size;
    const float* x     = (const float*)d_in[0];
    const float* qkv_w = (const float*)d_in[2];
    const float* out_w = (const float*)d_in[3];
    const float* out_b = (const float*)d_in[4];
    float* out = (float*)d_out;

    void *p_xh, *p_w1t, *p_w2t, *p_qkv, *p_attnh;
    cudaGetSymbolAddress(&p_xh, g_xh);
    cudaGetSymbolAddress(&p_w1t, g_w1t);
    cudaGetSymbolAddress(&p_w2t, g_w2t);
    cudaGetSymbolAddress(&p_qkv, g_qkv);
    cudaGetSymbolAddress(&p_attnh, g_attnh);

    cudaFuncSetAttribute(gemm_fp16,
                         cudaFuncAttributeMaxDynamicSharedMemorySize, GEMM_SMEM);
    cudaFuncSetAttribute(attn_fp16_kernel,
                         cudaFuncAttributeMaxDynamicSharedMemorySize, ATTN_SMEM);

    // 0) prep: x -> fp16, weights -> fp16 transposed [N][K]
    to_half_kernel<<<(NROW * D_) / 1024, 256>>>(x, (__half*)p_xh);
    transpose_to_half<<<dim3(3 * D_ / 32, D_ / 32), dim3(32, 8)>>>(
        qkv_w, (__half*)p_w1t, D_, 3 * D_);
    transpose_to_half<<<dim3(D_ / 32, D_ / 32), dim3(32, 8)>>>(
        out_w, (__half*)p_w2t, D_, D_);

    // 1) QKV projection (fp16 tensor cores, 128x256 tiles)
    gemm_fp16<<<dim3((3 * D_) / 256, NROW / 128), 256, GEMM_SMEM>>>(
        (const __half*)p_xh, (const __half*)p_w1t, nullptr, (float*)p_qkv,
        NROW, 3 * D_, D_);

    // 2) RoPE + split/transpose -> fp16
    rope_split_kernel<<<(BH_ * T_ * 32) / 256, 256>>>();

    // 3) causal flash attention (fp16 tensor cores)
    attn_fp16_kernel<<<dim3(T_ / 128, BH_), 128, ATTN_SMEM>>>();

    // 4) output projection + bias
    gemm_fp16<<<dim3(D_ / 256, NROW / 128), 256, GEMM_SMEM>>>(
        (const __half*)p_attnh, (const __half*)p_w2t, out_b, out, NROW, D_, D_);
}

// round 12
// speedup vs baseline: 2.4945x; 1.0333x over previous
#include <cuda_runtime.h>
#include <cuda_fp16.h>
#include <math.h>

// Problem constants
#define B_ 2
#define T_ 2048
#define D_ 1024
#define H_ 16
#define DH_ 64
#define NROW (B_ * T_)        // 4096
#define BH_ (B_ * H_)         // 32

// ---------------------------------------------------------------------------
// Scratch
// ---------------------------------------------------------------------------
__device__ __half g_xh [(size_t)NROW * D_];             // fp16 x
__device__ __half g_w1t[(size_t)(3 * D_) * D_];         // fp16 qkv_w transposed [N][K]
__device__ __half g_w2t[(size_t)D_ * D_];               // fp16 out_w transposed [N][K]
__device__ __half g_qkvh[(size_t)NROW * 3 * D_];        // [4096, 3072] fp16
__device__ __half g_qh[(size_t)BH_ * T_ * DH_];
__device__ __half g_kh[(size_t)BH_ * T_ * DH_];
__device__ __half g_vh[(size_t)BH_ * T_ * DH_];
__device__ __half g_attnh[(size_t)NROW * D_];           // [4096, 1024] fp16

// ---------------------------------------------------------------------------
// helpers
// ---------------------------------------------------------------------------
__device__ __forceinline__ unsigned pack_h2(float a, float b) {
    __half2 h = __floats2half2_rn(a, b);
    return *(unsigned*)&h;
}
__device__ __forceinline__ void mma_f16(float* c,
                                        unsigned a0, unsigned a1, unsigned a2, unsigned a3,
                                        unsigned b0, unsigned b1) {
    asm volatile("mma.sync.aligned.m16n8k16.row.col.f32.f16.f16.f32 "
                 "{%0,%1,%2,%3}, {%4,%5,%6,%7}, {%8,%9}, {%0,%1,%2,%3};"
                 : "+f"(c[0]), "+f"(c[1]), "+f"(c[2]), "+f"(c[3])
                 : "r"(a0), "r"(a1), "r"(a2), "r"(a3), "r"(b0), "r"(b1));
}
__device__ __forceinline__ void cp16(void* smem, const void* gmem) {
    unsigned s = (unsigned)__cvta_generic_to_shared(smem);
    asm volatile("cp.async.cg.shared.global [%0], [%1], 16;" :: "r"(s), "l"(gmem));
}
__device__ __forceinline__ void cp_commit() { asm volatile("cp.async.commit_group;"); }
__device__ __forceinline__ void cp_wait0()  { asm volatile("cp.async.wait_group 0;"); }

__device__ __forceinline__ void ldsm_x4(unsigned& r0, unsigned& r1,
                                        unsigned& r2, unsigned& r3, const void* p) {
    unsigned s = (unsigned)__cvta_generic_to_shared(p);
    asm volatile("ldmatrix.sync.aligned.m8n8.x4.shared.b16 {%0,%1,%2,%3}, [%4];"
                 : "=r"(r0), "=r"(r1), "=r"(r2), "=r"(r3) : "r"(s));
}
__device__ __forceinline__ void ldsm_x4_trans(unsigned& r0, unsigned& r1,
                                              unsigned& r2, unsigned& r3, const void* p) {
    unsigned s = (unsigned)__cvta_generic_to_shared(p);
    asm volatile("ldmatrix.sync.aligned.m8n8.x4.trans.shared.b16 {%0,%1,%2,%3}, [%4];"
                 : "=r"(r0), "=r"(r1), "=r"(r2), "=r"(r3) : "r"(s));
}

// ---------------------------------------------------------------------------
// prep kernels
// ---------------------------------------------------------------------------
__global__ void to_half_kernel(const float* __restrict__ in, __half* __restrict__ out)
{
    const int i = (blockIdx.x * blockDim.x + threadIdx.x) * 4;
    float4 v = *(const float4*)(in + i);
    *(__half2*)&out[i]     = __floats2half2_rn(v.x, v.y);
    *(__half2*)&out[i + 2] = __floats2half2_rn(v.z, v.w);
}

// in f32 [K][N] -> out fp16 [N][K]
__global__ void transpose_to_half(const float* __restrict__ in, __half* __restrict__ out,
                                  int K, int N)
{
    __shared__ float tile[32][33];
    const int n0 = blockIdx.x * 32;
    const int k0 = blockIdx.y * 32;
    const int tx = threadIdx.x;
    const int ty = threadIdx.y;
#pragma unroll
    for (int j = 0; j < 4; j++)
        tile[ty + 8 * j][tx] = in[(size_t)(k0 + ty + 8 * j) * N + n0 + tx];
    __syncthreads();
#pragma unroll
    for (int j = 0; j < 4; j++)
        out[(size_t)(n0 + ty + 8 * j) * K + k0 + tx] = __float2half(tile[tx][ty + 8 * j]);
}

// ---------------------------------------------------------------------------
// fp16 GEMM v3: block 128(M) x 128(N), BK=64, 128 threads = 4 warps (2m x 2n),
// warp tile 64x64. 2-stage cp.async. smem 72KB -> 2 CTAs/SM (barrier overlap).
// Output: f32 (C, +bias) or fp16 (Ch) — whichever pointer is non-null.
// ---------------------------------------------------------------------------
#define GP 72
#define GEMM_SMEM (2 * (128 + 128) * GP * 2)

__global__ void __launch_bounds__(128, 2)
gemm_fp16(const __half* __restrict__ A, const __half* __restrict__ Bt,
          const float* __restrict__ bias, float* __restrict__ C,
          __half* __restrict__ Ch, int M, int N, int K)
{
    extern __shared__ __half sh[];
    __half* Asm = sh;                    // [2][128][GP]
    __half* Bsm = sh + 2 * 128 * GP;     // [2][128][GP]

    const int bm = blockIdx.y * 128;
    const int bn = blockIdx.x * 128;
    const int tid = threadIdx.x;
    const int lane = tid & 31;
    const int w = tid >> 5;
    const int lrow = lane >> 2;
    const int lk = lane & 3;
    const int wm = (w & 1) * 64;
    const int wn = (w >> 1) * 64;

    const int a_row_off = lane & 15;
    const int a_col_off = (lane >> 4) * 8;
    const int b_row_off = (lane >> 4) * 8 + (lane & 7);
    const int b_col_off = ((lane >> 3) & 1) * 8;

    float acc[4][8][4];
#pragma unroll
    for (int mt = 0; mt < 4; mt++)
#pragma unroll
        for (int nt = 0; nt < 8; nt++)
#pragma unroll
            for (int i = 0; i < 4; i++) acc[mt][nt][i] = 0.0f;

    const int ntiles = K / 64;

    // prologue: stage tile 0 (A: 1024 chunks, B: 1024 chunks; 8 each/thread)
    {
#pragma unroll
        for (int i = 0; i < 8; i++) {
            const int e = tid + i * 128;
            const int r = e >> 3;
            const int c = (e & 7) * 8;
            cp16(&Asm[r * GP + c], A + (size_t)(bm + r) * K + c);
            cp16(&Bsm[r * GP + c], Bt + (size_t)(bn + r) * K + c);
        }
        cp_commit();
    }

    for (int t = 0; t < ntiles; t++) {
        const int s = t & 1;
        cp_wait0();
        __syncthreads();

        if (t + 1 < ntiles) {
            const int kn = (t + 1) * 64;
            __half* Ad = Asm + (s ^ 1) * 128 * GP;
            __half* Bd = Bsm + (s ^ 1) * 128 * GP;
#pragma unroll
            for (int i = 0; i < 8; i++) {
                const int e = tid + i * 128;
                const int r = e >> 3;
                const int c = (e & 7) * 8;
                cp16(&Ad[r * GP + c], A + (size_t)(bm + r) * K + kn + c);
                cp16(&Bd[r * GP + c], Bt + (size_t)(bn + r) * K + kn + c);
            }
            cp_commit();
        }

        const __half* Ah = Asm + s * 128 * GP;
        const __half* Bh = Bsm + s * 128 * GP;
#pragma unroll
        for (int kc = 0; kc < 4; kc++) {
            const int kh = kc * 16;
            unsigned af[4][4];
#pragma unroll
            for (int mt = 0; mt < 4; mt++)
                ldsm_x4(af[mt][0], af[mt][1], af[mt][2], af[mt][3],
                        &Ah[(wm + mt * 16 + a_row_off) * GP + kh + a_col_off]);
            unsigned bf[8][2];
#pragma unroll
            for (int ntp = 0; ntp < 4; ntp++) {
                unsigned r0, r1, r2, r3;
                ldsm_x4(r0, r1, r2, r3,
                        &Bh[(wn + ntp * 16 + b_row_off) * GP + kh + b_col_off]);
                bf[2 * ntp][0] = r0;     bf[2 * ntp][1] = r1;
                bf[2 * ntp + 1][0] = r2; bf[2 * ntp + 1][1] = r3;
            }
#pragma unroll
            for (int nt = 0; nt < 8; nt++)
#pragma unroll
                for (int mt = 0; mt < 4; mt++)
                    mma_f16(acc[mt][nt], af[mt][0], af[mt][1], af[mt][2], af[mt][3],
                            bf[nt][0], bf[nt][1]);
        }
        __syncthreads();
    }

#pragma unroll
    for (int mt = 0; mt < 4; mt++) {
        const int row0 = bm + wm + mt * 16 + lrow;
#pragma unroll
        for (int nt = 0; nt < 8; nt++) {
            const int col = bn + wn + nt * 8 + lk * 2;
            if (Ch) {
                *(__half2*)&Ch[(size_t)row0 * N + col] =
                    __floats2half2_rn(acc[mt][nt][0], acc[mt][nt][1]);
                *(__half2*)&Ch[(size_t)(row0 + 8) * N + col] =
                    __floats2half2_rn(acc[mt][nt][2], acc[mt][nt][3]);
            } else {
                float bx = 0.f, by = 0.f;
                if (bias) { bx = bias[col]; by = bias[col + 1]; }
                *(float2*)&C[(size_t)row0 * N + col] =
                    make_float2(acc[mt][nt][0] + bx, acc[mt][nt][1] + by);
                *(float2*)&C[(size_t)(row0 + 8) * N + col] =
                    make_float2(acc[mt][nt][2] + bx, acc[mt][nt][3] + by);
            }
        }
    }
}

// ---------------------------------------------------------------------------
// RoPE + split + transpose (fp16 in/out). q pre-scaled by 1/8.
// ---------------------------------------------------------------------------
__global__ void rope_split_kernel()
{
    const int idx = blockIdx.x * blockDim.x + threadIdx.x;
    const int d2 = idx & 31;
    const int t  = (idx >> 5) & (T_ - 1);
    const int bh = idx >> 16;
    const int h = bh & (H_ - 1);
    const int b = bh >> 4;

    const __half* row = g_qkvh + ((size_t)(b * T_ + t)) * (3 * D_) + h * DH_;
    const float q0 = __half2float(row[d2]);
    const float q1 = __half2float(row[d2 + 32]);
    const float k0 = __half2float(row[D_ + d2]);
    const float k1 = __half2float(row[D_ + d2 + 32]);
    const __half v0 = row[2 * D_ + d2];
    const __half v1 = row[2 * D_ + d2 + 32];

    const float inv = 1.0f / powf(10000.0f, (float)d2 * (1.0f / 32.0f));
    const float ang = (float)t * inv;
    float sn, cs;
    sincosf(ang, &sn, &cs);

    const size_t obase = ((size_t)bh * T_ + t) * DH_;
    g_qh[obase + d2]      = __float2half((q0 * cs - q1 * sn) * 0.125f);
    g_qh[obase + d2 + 32] = __float2half((q1 * cs + q0 * sn) * 0.125f);
    g_kh[obase + d2]      = __float2half(k0 * cs - k1 * sn);
    g_kh[obase + d2 + 32] = __float2half(k1 * cs + k0 * sn);
    g_vh[obase + d2]      = v0;
    g_vh[obase + d2 + 32] = v1;
}

// ---------------------------------------------------------------------------
// fp16 tensor-core flash attention (R8/R11 best, unchanged).
// ---------------------------------------------------------------------------
#define AP 72
#define ATTN_SMEM ((128 * AP + 4 * 64 * AP) * 2)

__global__ void __launch_bounds__(128, 3)
attn_fp16_kernel()
{
    extern __shared__ __half sh[];
    __half* qs = sh;                         // [128][72]
    __half* kbuf[2] = { sh + 128 * AP, sh + 128 * AP + 2 * 64 * AP };
    __half* vbuf[2] = { sh + 128 * AP + 64 * AP, sh + 128 * AP + 3 * 64 * AP };

    const int qt = (T_ / 128 - 1) - blockIdx.x;   // heavy blocks first
    const int bh = blockIdx.y;
    const int tid = threadIdx.x;
    const int lane = tid & 31;
    const int w = tid >> 5;
    const int lrow = lane >> 2;
    const int lk = lane & 3;
    const int wrow = w * 32;

    const int a_row_off = lane & 15;
    const int a_col_off = (lane >> 4) * 8;
    const int b_row_off = (lane >> 4) * 8 + (lane & 7);
    const int b_col_off = ((lane >> 3) & 1) * 8;

    const __half* Qb = g_qh + ((size_t)bh * T_ + qt * 128) * DH_;
    const __half* Kb = g_kh + (size_t)bh * T_ * DH_;
    const __half* Vb = g_vh + (size_t)bh * T_ * DH_;

#pragma unroll
    for (int i = 0; i < 8; i++) {
        const int e = tid + i * 128;
        const int r = e >> 3;
        const int c = (e & 7) * 8;
        cp16(&qs[r * AP + c], &Qb[r * 64 + c]);
    }
#pragma unroll
    for (int i = 0; i < 4; i++) {
        const int e = tid + i * 128;
        const int r = e >> 3;
        const int c = (e & 7) * 8;
        cp16(&kbuf[0][r * AP + c], Kb + (size_t)r * 64 + c);
        cp16(&vbuf[0][r * AP + c], Vb + (size_t)r * 64 + c);
    }
    cp_commit();

    float m[2][2], l[2][2];
    float oacc[2][8][4];
#pragma unroll
    for (int mg = 0; mg < 2; mg++) {
        m[mg][0] = -1e30f; m[mg][1] = -1e30f;
        l[mg][0] = 0.f;    l[mg][1] = 0.f;
#pragma unroll
        for (int nt = 0; nt < 8; nt++)
#pragma unroll
            for (int i = 0; i < 4; i++) oacc[mg][nt][i] = 0.f;
    }

    const int ktmax = 2 * qt + 1;
    for (int kt = 0; kt <= ktmax; kt++) {
        const int s = kt & 1;
        cp_wait0();
        __syncthreads();

        if (kt < ktmax) {
#pragma unroll
            for (int i = 0; i < 4; i++) {
                const int e = tid + i * 128;
                const int r = e >> 3;
                const int c = (e & 7) * 8;
                cp16(&kbuf[s ^ 1][r * AP + c], Kb + (size_t)((kt + 1) * 64 + r) * 64 + c);
                cp16(&vbuf[s ^ 1][r * AP + c], Vb + (size_t)((kt + 1) * 64 + r) * 64 + c);
            }
            cp_commit();
        }

        const __half* ks = kbuf[s];
        const __half* vs = vbuf[s];

        float sacc[2][8][4];
#pragma unroll
        for (int mg = 0; mg < 2; mg++)
#pragma unroll
            for (int nt = 0; nt < 8; nt++)
#pragma unroll
                for (int i = 0; i < 4; i++) sacc[mg][nt][i] = 0.f;

#pragma unroll
        for (int kc = 0; kc < 4; kc++) {
            const int kh = kc * 16;
            unsigned af[2][4];
#pragma unroll
            for (int mg = 0; mg < 2; mg++)
                ldsm_x4(af[mg][0], af[mg][1], af[mg][2], af[mg][3],
                        &qs[(wrow + mg * 16 + a_row_off) * AP + kh + a_col_off]);
            unsigned bf[8][2];
#pragma unroll
            for (int ntp = 0; ntp < 4; ntp++) {
                unsigned r0, r1, r2, r3;
                ldsm_x4(r0, r1, r2, r3,
                        &ks[(ntp * 16 + b_row_off) * AP + kh + b_col_off]);
                bf[2 * ntp][0] = r0;     bf[2 * ntp][1] = r1;
                bf[2 * ntp + 1][0] = r2; bf[2 * ntp + 1][1] = r3;
            }
#pragma unroll
            for (int nt = 0; nt < 8; nt++)
#pragma unroll
                for (int mg = 0; mg < 2; mg++)
                    mma_f16(sacc[mg][nt], af[mg][0], af[mg][1], af[mg][2], af[mg][3],
                            bf[nt][0], bf[nt][1]);
        }

        if (kt * 64 + 63 > qt * 128 + wrow) {
#pragma unroll
            for (int mg = 0; mg < 2; mg++) {
                const int rg0 = qt * 128 + wrow + mg * 16 + lrow;
                const int rg1 = rg0 + 8;
#pragma unroll
                for (int nt = 0; nt < 8; nt++) {
                    const int cg = kt * 64 + nt * 8 + lk * 2;
                    if (cg > rg0)     sacc[mg][nt][0] = -1e30f;
                    if (cg + 1 > rg0) sacc[mg][nt][1] = -1e30f;
                    if (cg > rg1)     sacc[mg][nt][2] = -1e30f;
                    if (cg + 1 > rg1) sacc[mg][nt][3] = -1e30f;
                }
            }
        }

        unsigned pk01[2][8], pk23[2][8];
#pragma unroll
        for (int mg = 0; mg < 2; mg++) {
            float tm0 = -1e30f, tm1 = -1e30f;
#pragma unroll
            for (int nt = 0; nt < 8; nt++) {
                tm0 = fmaxf(tm0, fmaxf(sacc[mg][nt][0], sacc[mg][nt][1]));
                tm1 = fmaxf(tm1, fmaxf(sacc[mg][nt][2], sacc[mg][nt][3]));
            }
            tm0 = fmaxf(tm0, __shfl_xor_sync(0xffffffffu, tm0, 1));
            tm0 = fmaxf(tm0, __shfl_xor_sync(0xffffffffu, tm0, 2));
            tm1 = fmaxf(tm1, __shfl_xor_sync(0xffffffffu, tm1, 1));
            tm1 = fmaxf(tm1, __shfl_xor_sync(0xffffffffu, tm1, 2));

            const float mn0 = fmaxf(m[mg][0], tm0);
            const float mn1 = fmaxf(m[mg][1], tm1);
            const float corr0 = __expf(m[mg][0] - mn0);
            const float corr1 = __expf(m[mg][1] - mn1);
            m[mg][0] = mn0; m[mg][1] = mn1;

            float sum0 = 0.f, sum1 = 0.f;
#pragma unroll
            for (int nt = 0; nt < 8; nt++) {
                const float p00 = __expf(sacc[mg][nt][0] - mn0);
                const float p01 = __expf(sacc[mg][nt][1] - mn0);
                const float p10 = __expf(sacc[mg][nt][2] - mn1);
                const float p11 = __expf(sacc[mg][nt][3] - mn1);
                sum0 += p00 + p01;
                sum1 += p10 + p11;
                pk01[mg][nt] = pack_h2(p00, p01);
                pk23[mg][nt] = pack_h2(p10, p11);
            }
            sum0 += __shfl_xor_sync(0xffffffffu, sum0, 1);
            sum0 += __shfl_xor_sync(0xffffffffu, sum0, 2);
            sum1 += __shfl_xor_sync(0xffffffffu, sum1, 1);
            sum1 += __shfl_xor_sync(0xffffffffu, sum1, 2);
            l[mg][0] = l[mg][0] * corr0 + sum0;
            l[mg][1] = l[mg][1] * corr1 + sum1;

#pragma unroll
            for (int nt = 0; nt < 8; nt++) {
                oacc[mg][nt][0] *= corr0;
                oacc[mg][nt][1] *= corr0;
                oacc[mg][nt][2] *= corr1;
                oacc[mg][nt][3] *= corr1;
            }
        }

#pragma unroll
        for (int kc = 0; kc < 4; kc++) {
            const int g = lane >> 3;
            const int li = lane & 7;
            const int vrow = kc * 16 + (g & 1) * 8 + li;
#pragma unroll
            for (int ntp = 0; ntp < 4; ntp++) {
                const int vcol = ntp * 16 + (g >> 1) * 8;
                unsigned r0, r1, r2, r3;
                ldsm_x4_trans(r0, r1, r2, r3, &vs[vrow * AP + vcol]);
#pragma unroll
                for (int mg = 0; mg < 2; mg++) {
                    mma_f16(oacc[mg][ntp * 2],
                            pk01[mg][2 * kc], pk23[mg][2 * kc],
                            pk01[mg][2 * kc + 1], pk23[mg][2 * kc + 1], r0, r1);
                    mma_f16(oacc[mg][ntp * 2 + 1],
                            pk01[mg][2 * kc], pk23[mg][2 * kc],
                            pk01[mg][2 * kc + 1], pk23[mg][2 * kc + 1], r2, r3);
                }
            }
        }
    }

    const int b = bh >> 4;
    const int h = bh & (H_ - 1);
#pragma unroll
    for (int mg = 0; mg < 2; mg++) {
        const float il0 = 1.0f / l[mg][0];
        const float il1 = 1.0f / l[mg][1];
        const int t0 = qt * 128 + wrow + mg * 16 + lrow;
        const int t1 = t0 + 8;
        const size_t base0 = ((size_t)(b * T_ + t0)) * D_ + h * DH_;
        const size_t base1 = ((size_t)(b * T_ + t1)) * D_ + h * DH_;
#pragma unroll
        for (int nt = 0; nt < 8; nt++) {
            const int c0 = nt * 8 + lk * 2;
            *(__half2*)&g_attnh[base0 + c0] =
                __floats2half2_rn(oacc[mg][nt][0] * il0, oacc[mg][nt][1] * il0);
            *(__half2*)&g_attnh[base1 + c0] =
                __floats2half2_rn(oacc[mg][nt][2] * il1, oacc[mg][nt][3] * il1);
        }
    }
}

// ---------------------------------------------------------------------------
// kernel_launch
// ---------------------------------------------------------------------------
extern "C" void kernel_launch(void* const* d_in, const int* in_sizes, int n_in,
                              void* d_out, int out_size)
{
    (void)in_sizes; (void)n_in; (void)out_size;
    const float* x     = (const float*)d_in[0];
    const float* qkv_w = (const float*)d_in[2];
    const float* out_w = (const float*)d_in[3];
    const float* out_b = (const float*)d_in[4];
    float* out = (float*)d_out;

    void *p_xh, *p_w1t, *p_w2t, *p_qkvh, *p_attnh;
    cudaGetSymbolAddress(&p_xh, g_xh);
    cudaGetSymbolAddress(&p_w1t, g_w1t);
    cudaGetSymbolAddress(&p_w2t, g_w2t);
    cudaGetSymbolAddress(&p_qkvh, g_qkvh);
    cudaGetSymbolAddress(&p_attnh, g_attnh);

    cudaFuncSetAttribute(gemm_fp16,
                         cudaFuncAttributeMaxDynamicSharedMemorySize, GEMM_SMEM);
    cudaFuncSetAttribute(attn_fp16_kernel,
                         cudaFuncAttributeMaxDynamicSharedMemorySize, ATTN_SMEM);

    // 0) prep: x -> fp16, weights -> fp16 transposed [N][K]
    to_half_kernel<<<(NROW * D_) / 1024, 256>>>(x, (__half*)p_xh);
    transpose_to_half<<<dim3(3 * D_ / 32, D_ / 32), dim3(32, 8)>>>(
        qkv_w, (__half*)p_w1t, D_, 3 * D_);
    transpose_to_half<<<dim3(D_ / 32, D_ / 32), dim3(32, 8)>>>(
        out_w, (__half*)p_w2t, D_, D_);

    // 1) QKV projection -> fp16 output
    gemm_fp16<<<dim3((3 * D_) / 128, NROW / 128), 128, GEMM_SMEM>>>(
        (const __half*)p_xh, (const __half*)p_w1t, nullptr, nullptr,
        (__half*)p_qkvh, NROW, 3 * D_, D_);

    // 2) RoPE + split/transpose (fp16 in/out)
    rope_split_kernel<<<(BH_ * T_ * 32) / 256, 256>>>();

    // 3) causal flash attention (fp16 tensor cores)
    attn_fp16_kernel<<<dim3(T_ / 128, BH_), 128, ATTN_SMEM>>>();

    // 4) output projection + bias -> f32
    gemm_fp16<<<dim3(D_ / 128, NROW / 128), 128, GEMM_SMEM>>>(
        (const __half*)p_attnh, (const __half*)p_w2t, out_b, out,
        nullptr, NROW, D_, D_);
}

// round 13
// speedup vs baseline: 2.5210x; 1.0106x over previous
#include <cuda_runtime.h>
#include <cuda_fp16.h>
#include <math.h>

// Problem constants
#define B_ 2
#define T_ 2048
#define D_ 1024
#define H_ 16
#define DH_ 64
#define NROW (B_ * T_)        // 4096
#define BH_ (B_ * H_)         // 32

// ---------------------------------------------------------------------------
// Scratch
// ---------------------------------------------------------------------------
__device__ __half g_xh [(size_t)NROW * D_];             // fp16 x
__device__ __half g_w1t[(size_t)(3 * D_) * D_];         // fp16 qkv_w transposed [N][K]
__device__ __half g_w2t[(size_t)D_ * D_];               // fp16 out_w transposed [N][K]
__device__ __half g_qh[(size_t)BH_ * T_ * DH_];
__device__ __half g_kh[(size_t)BH_ * T_ * DH_];
__device__ __half g_vh[(size_t)BH_ * T_ * DH_];
__device__ __half g_attnh[(size_t)NROW * D_];           // [4096, 1024] fp16
__device__ float2 g_rt[(size_t)T_ * 32];                // rope (cos,sin) table

// ---------------------------------------------------------------------------
// helpers
// ---------------------------------------------------------------------------
__device__ __forceinline__ unsigned pack_h2(float a, float b) {
    __half2 h = __floats2half2_rn(a, b);
    return *(unsigned*)&h;
}
__device__ __forceinline__ void mma_f16(float* c,
                                        unsigned a0, unsigned a1, unsigned a2, unsigned a3,
                                        unsigned b0, unsigned b1) {
    asm volatile("mma.sync.aligned.m16n8k16.row.col.f32.f16.f16.f32 "
                 "{%0,%1,%2,%3}, {%4,%5,%6,%7}, {%8,%9}, {%0,%1,%2,%3};"
                 : "+f"(c[0]), "+f"(c[1]), "+f"(c[2]), "+f"(c[3])
                 : "r"(a0), "r"(a1), "r"(a2), "r"(a3), "r"(b0), "r"(b1));
}
__device__ __forceinline__ void cp16(void* smem, const void* gmem) {
    unsigned s = (unsigned)__cvta_generic_to_shared(smem);
    asm volatile("cp.async.cg.shared.global [%0], [%1], 16;" :: "r"(s), "l"(gmem));
}
__device__ __forceinline__ void cp_commit() { asm volatile("cp.async.commit_group;"); }
__device__ __forceinline__ void cp_wait0()  { asm volatile("cp.async.wait_group 0;"); }

__device__ __forceinline__ void ldsm_x4(unsigned& r0, unsigned& r1,
                                        unsigned& r2, unsigned& r3, const void* p) {
    unsigned s = (unsigned)__cvta_generic_to_shared(p);
    asm volatile("ldmatrix.sync.aligned.m8n8.x4.shared.b16 {%0,%1,%2,%3}, [%4];"
                 : "=r"(r0), "=r"(r1), "=r"(r2), "=r"(r3) : "r"(s));
}
__device__ __forceinline__ void ldsm_x4_trans(unsigned& r0, unsigned& r1,
                                              unsigned& r2, unsigned& r3, const void* p) {
    unsigned s = (unsigned)__cvta_generic_to_shared(p);
    asm volatile("ldmatrix.sync.aligned.m8n8.x4.trans.shared.b16 {%0,%1,%2,%3}, [%4];"
                 : "=r"(r0), "=r"(r1), "=r"(r2), "=r"(r3) : "r"(s));
}

// ---------------------------------------------------------------------------
// prep kernels
// ---------------------------------------------------------------------------
__global__ void to_half_kernel(const float* __restrict__ in, __half* __restrict__ out)
{
    const int i = (blockIdx.x * blockDim.x + threadIdx.x) * 4;
    float4 v = *(const float4*)(in + i);
    *(__half2*)&out[i]     = __floats2half2_rn(v.x, v.y);
    *(__half2*)&out[i + 2] = __floats2half2_rn(v.z, v.w);
}

// in f32 [K][N] -> out fp16 [N][K]
__global__ void transpose_to_half(const float* __restrict__ in, __half* __restrict__ out,
                                  int K, int N)
{
    __shared__ float tile[32][33];
    const int n0 = blockIdx.x * 32;
    const int k0 = blockIdx.y * 32;
    const int tx = threadIdx.x;
    const int ty = threadIdx.y;
#pragma unroll
    for (int j = 0; j < 4; j++)
        tile[ty + 8 * j][tx] = in[(size_t)(k0 + ty + 8 * j) * N + n0 + tx];
    __syncthreads();
#pragma unroll
    for (int j = 0; j < 4; j++)
        out[(size_t)(n0 + ty + 8 * j) * K + k0 + tx] = __float2half(tile[tx][ty + 8 * j]);
}

// rope table: g_rt[t*32 + d2] = (cos, sin) of t / 10000^(d2/32)
__global__ void rope_table_kernel()
{
    const int idx = blockIdx.x * blockDim.x + threadIdx.x;   // 0..65535
    const int t = idx >> 5;
    const int d2 = idx & 31;
    const float inv = 1.0f / powf(10000.0f, (float)d2 * (1.0f / 32.0f));
    float sn, cs;
    sincosf((float)t * inv, &sn, &cs);
    g_rt[idx] = make_float2(cs, sn);
}

// ---------------------------------------------------------------------------
// fp16 GEMM: block 128x128, BK=64, 128 threads = 4 warps (2m x 2n),
// warp tile 64x64. 2-stage cp.async.
// mode 0: C(f32) = A@Bt + bias (out projection)
// mode 1: fused QKV epilogue — applies RoPE to q/k in registers (partner
//         column d+32 lives in acc[mt][nt+4], same thread) and scatters
//         q/k/v directly into g_qh/g_kh/g_vh [bh,t,d] fp16.
// ---------------------------------------------------------------------------
#define GP 72
#define GEMM_SMEM (2 * (128 + 128) * GP * 2)

__global__ void __launch_bounds__(128, 2)
gemm_fp16(const __half* __restrict__ A, const __half* __restrict__ Bt,
          const float* __restrict__ bias, float* __restrict__ C,
          int mode, int M, int N, int K)
{
    extern __shared__ __half sh[];
    __half* Asm = sh;                    // [2][128][GP]
    __half* Bsm = sh + 2 * 128 * GP;     // [2][128][GP]

    const int bm = blockIdx.y * 128;
    const int bn = blockIdx.x * 128;
    const int tid = threadIdx.x;
    const int lane = tid & 31;
    const int w = tid >> 5;
    const int lrow = lane >> 2;
    const int lk = lane & 3;
    const int wm = (w & 1) * 64;
    const int wn = (w >> 1) * 64;

    const int a_row_off = lane & 15;
    const int a_col_off = (lane >> 4) * 8;
    const int b_row_off = (lane >> 4) * 8 + (lane & 7);
    const int b_col_off = ((lane >> 3) & 1) * 8;

    float acc[4][8][4];
#pragma unroll
    for (int mt = 0; mt < 4; mt++)
#pragma unroll
        for (int nt = 0; nt < 8; nt++)
#pragma unroll
            for (int i = 0; i < 4; i++) acc[mt][nt][i] = 0.0f;

    const int ntiles = K / 64;

    // prologue: stage tile 0
    {
#pragma unroll
        for (int i = 0; i < 8; i++) {
            const int e = tid + i * 128;
            const int r = e >> 3;
            const int c = (e & 7) * 8;
            cp16(&Asm[r * GP + c], A + (size_t)(bm + r) * K + c);
            cp16(&Bsm[r * GP + c], Bt + (size_t)(bn + r) * K + c);
        }
        cp_commit();
    }

    for (int t = 0; t < ntiles; t++) {
        const int s = t & 1;
        cp_wait0();
        __syncthreads();

        if (t + 1 < ntiles) {
            const int kn = (t + 1) * 64;
            __half* Ad = Asm + (s ^ 1) * 128 * GP;
            __half* Bd = Bsm + (s ^ 1) * 128 * GP;
#pragma unroll
            for (int i = 0; i < 8; i++) {
                const int e = tid + i * 128;
                const int r = e >> 3;
                const int c = (e & 7) * 8;
                cp16(&Ad[r * GP + c], A + (size_t)(bm + r) * K + kn + c);
                cp16(&Bd[r * GP + c], Bt + (size_t)(bn + r) * K + kn + c);
            }
            cp_commit();
        }

        const __half* Ah = Asm + s * 128 * GP;
        const __half* Bh = Bsm + s * 128 * GP;
#pragma unroll
        for (int kc = 0; kc < 4; kc++) {
            const int kh = kc * 16;
            unsigned af[4][4];
#pragma unroll
            for (int mt = 0; mt < 4; mt++)
                ldsm_x4(af[mt][0], af[mt][1], af[mt][2], af[mt][3],
                        &Ah[(wm + mt * 16 + a_row_off) * GP + kh + a_col_off]);
            unsigned bf[8][2];
#pragma unroll
            for (int ntp = 0; ntp < 4; ntp++) {
                unsigned r0, r1, r2, r3;
                ldsm_x4(r0, r1, r2, r3,
                        &Bh[(wn + ntp * 16 + b_row_off) * GP + kh + b_col_off]);
                bf[2 * ntp][0] = r0;     bf[2 * ntp][1] = r1;
                bf[2 * ntp + 1][0] = r2; bf[2 * ntp + 1][1] = r3;
            }
#pragma unroll
            for (int nt = 0; nt < 8; nt++)
#pragma unroll
                for (int mt = 0; mt < 4; mt++)
                    mma_f16(acc[mt][nt], af[mt][0], af[mt][1], af[mt][2], af[mt][3],
                            bf[nt][0], bf[nt][1]);
        }
        __syncthreads();
    }

    // ------------------------- epilogue -------------------------
    if (mode == 0) {
#pragma unroll
        for (int mt = 0; mt < 4; mt++) {
            const int row0 = bm + wm + mt * 16 + lrow;
#pragma unroll
            for (int nt = 0; nt < 8; nt++) {
                const int col = bn + wn + nt * 8 + lk * 2;
                const float bx = bias ? bias[col] : 0.f;
                const float by = bias ? bias[col + 1] : 0.f;
                *(float2*)&C[(size_t)row0 * N + col] =
                    make_float2(acc[mt][nt][0] + bx, acc[mt][nt][1] + by);
                *(float2*)&C[(size_t)(row0 + 8) * N + col] =
                    make_float2(acc[mt][nt][2] + bx, acc[mt][nt][3] + by);
            }
        }
        return;
    }

    // mode 1: fused RoPE + scatter. Warp tile covers exactly one (s,h).
    const int colbase = bn + wn;          // multiple of 64
    const int sec = colbase >> 10;        // 0=q, 1=k, 2=v
    const int h = (colbase >> 6) & (H_ - 1);

    if (sec == 2) {
        // v: plain fp16 store to [bh, t, d]
#pragma unroll
        for (int mt = 0; mt < 4; mt++) {
            const int row0 = bm + wm + mt * 16 + lrow;
#pragma unroll
            for (int half = 0; half < 2; half++) {
                const int row = row0 + 8 * half;
                const int b = row >> 11;
                const int tt = row & (T_ - 1);
                const size_t base = ((size_t)(b * H_ + h) * T_ + tt) * DH_;
#pragma unroll
                for (int nt = 0; nt < 8; nt++) {
                    const int d = nt * 8 + lk * 2;
                    *(__half2*)&g_vh[base + d] =
                        __floats2half2_rn(acc[mt][nt][2 * half], acc[mt][nt][2 * half + 1]);
                }
            }
        }
    } else {
        __half* dst = (sec == 0) ? g_qh : g_kh;
        const float scale = (sec == 0) ? 0.125f : 1.0f;
#pragma unroll
        for (int mt = 0; mt < 4; mt++) {
            const int row0 = bm + wm + mt * 16 + lrow;
#pragma unroll
            for (int half = 0; half < 2; half++) {
                const int row = row0 + 8 * half;
                const int b = row >> 11;
                const int tt = row & (T_ - 1);
                const size_t base = ((size_t)(b * H_ + h) * T_ + tt) * DH_;
#pragma unroll
                for (int nt = 0; nt < 4; nt++) {
                    const int d = nt * 8 + lk * 2;     // 0..31 region
                    const float2 cs0 = g_rt[tt * 32 + d];
                    const float2 cs1 = g_rt[tt * 32 + d + 1];
                    const float a0 = acc[mt][nt][2 * half];
                    const float a1 = acc[mt][nt][2 * half + 1];
                    const float p0 = acc[mt][nt + 4][2 * half];
                    const float p1 = acc[mt][nt + 4][2 * half + 1];
                    const float lo0 = (a0 * cs0.x - p0 * cs0.y) * scale;
                    const float lo1 = (a1 * cs1.x - p1 * cs1.y) * scale;
                    const float hi0 = (p0 * cs0.x + a0 * cs0.y) * scale;
                    const float hi1 = (p1 * cs1.x + a1 * cs1.y) * scale;
                    *(__half2*)&dst[base + d]      = __floats2half2_rn(lo0, lo1);
                    *(__half2*)&dst[base + d + 32] = __floats2half2_rn(hi0, hi1);
                }
            }
        }
    }
}

// ---------------------------------------------------------------------------
// fp16 tensor-core flash attention (R8/R11 best, unchanged).
// ---------------------------------------------------------------------------
#define AP 72
#define ATTN_SMEM ((128 * AP + 4 * 64 * AP) * 2)

__global__ void __launch_bounds__(128, 3)
attn_fp16_kernel()
{
    extern __shared__ __half sh[];
    __half* qs = sh;                         // [128][72]
    __half* kbuf[2] = { sh + 128 * AP, sh + 128 * AP + 2 * 64 * AP };
    __half* vbuf[2] = { sh + 128 * AP + 64 * AP, sh + 128 * AP + 3 * 64 * AP };

    const int qt = (T_ / 128 - 1) - blockIdx.x;   // heavy blocks first
    const int bh = blockIdx.y;
    const int tid = threadIdx.x;
    const int lane = tid & 31;
    const int w = tid >> 5;
    const int lrow = lane >> 2;
    const int lk = lane & 3;
    const int wrow = w * 32;

    const int a_row_off = lane & 15;
    const int a_col_off = (lane >> 4) * 8;
    const int b_row_off = (lane >> 4) * 8 + (lane & 7);
    const int b_col_off = ((lane >> 3) & 1) * 8;

    const __half* Qb = g_qh + ((size_t)bh * T_ + qt * 128) * DH_;
    const __half* Kb = g_kh + (size_t)bh * T_ * DH_;
    const __half* Vb = g_vh + (size_t)bh * T_ * DH_;

#pragma unroll
    for (int i = 0; i < 8; i++) {
        const int e = tid + i * 128;
        const int r = e >> 3;
        const int c = (e & 7) * 8;
        cp16(&qs[r * AP + c], &Qb[r * 64 + c]);
    }
#pragma unroll
    for (int i = 0; i < 4; i++) {
        const int e = tid + i * 128;
        const int r = e >> 3;
        const int c = (e & 7) * 8;
        cp16(&kbuf[0][r * AP + c], Kb + (size_t)r * 64 + c);
        cp16(&vbuf[0][r * AP + c], Vb + (size_t)r * 64 + c);
    }
    cp_commit();

    float m[2][2], l[2][2];
    float oacc[2][8][4];
#pragma unroll
    for (int mg = 0; mg < 2; mg++) {
        m[mg][0] = -1e30f; m[mg][1] = -1e30f;
        l[mg][0] = 0.f;    l[mg][1] = 0.f;
#pragma unroll
        for (int nt = 0; nt < 8; nt++)
#pragma unroll
            for (int i = 0; i < 4; i++) oacc[mg][nt][i] = 0.f;
    }

    const int ktmax = 2 * qt + 1;
    for (int kt = 0; kt <= ktmax; kt++) {
        const int s = kt & 1;
        cp_wait0();
        __syncthreads();

        if (kt < ktmax) {
#pragma unroll
            for (int i = 0; i < 4; i++) {
                const int e = tid + i * 128;
                const int r = e >> 3;
                const int c = (e & 7) * 8;
                cp16(&kbuf[s ^ 1][r * AP + c], Kb + (size_t)((kt + 1) * 64 + r) * 64 + c);
                cp16(&vbuf[s ^ 1][r * AP + c], Vb + (size_t)((kt + 1) * 64 + r) * 64 + c);
            }
            cp_commit();
        }

        const __half* ks = kbuf[s];
        const __half* vs = vbuf[s];

        float sacc[2][8][4];
#pragma unroll
        for (int mg = 0; mg < 2; mg++)
#pragma unroll
            for (int nt = 0; nt < 8; nt++)
#pragma unroll
                for (int i = 0; i < 4; i++) sacc[mg][nt][i] = 0.f;

#pragma unroll
        for (int kc = 0; kc < 4; kc++) {
            const int kh = kc * 16;
            unsigned af[2][4];
#pragma unroll
            for (int mg = 0; mg < 2; mg++)
                ldsm_x4(af[mg][0], af[mg][1], af[mg][2], af[mg][3],
                        &qs[(wrow + mg * 16 + a_row_off) * AP + kh + a_col_off]);
            unsigned bf[8][2];
#pragma unroll
            for (int ntp = 0; ntp < 4; ntp++) {
                unsigned r0, r1, r2, r3;
                ldsm_x4(r0, r1, r2, r3,
                        &ks[(ntp * 16 + b_row_off) * AP + kh + b_col_off]);
                bf[2 * ntp][0] = r0;     bf[2 * ntp][1] = r1;
                bf[2 * ntp + 1][0] = r2; bf[2 * ntp + 1][1] = r3;
            }
#pragma unroll
            for (int nt = 0; nt < 8; nt++)
#pragma unroll
                for (int mg = 0; mg < 2; mg++)
                    mma_f16(sacc[mg][nt], af[mg][0], af[mg][1], af[mg][2], af[mg][3],
                            bf[nt][0], bf[nt][1]);
        }

        if (kt * 64 + 63 > qt * 128 + wrow) {
#pragma unroll
            for (int mg = 0; mg < 2; mg++) {
                const int rg0 = qt * 128 + wrow + mg * 16 + lrow;
                const int rg1 = rg0 + 8;
#pragma unroll
                for (int nt = 0; nt < 8; nt++) {
                    const int cg = kt * 64 + nt * 8 + lk * 2;
                    if (cg > rg0)     sacc[mg][nt][0] = -1e30f;
                    if (cg + 1 > rg0) sacc[mg][nt][1] = -1e30f;
                    if (cg > rg1)     sacc[mg][nt][2] = -1e30f;
                    if (cg + 1 > rg1) sacc[mg][nt][3] = -1e30f;
                }
            }
        }

        unsigned pk01[2][8], pk23[2][8];
#pragma unroll
        for (int mg = 0; mg < 2; mg++) {
            float tm0 = -1e30f, tm1 = -1e30f;
#pragma unroll
            for (int nt = 0; nt < 8; nt++) {
                tm0 = fmaxf(tm0, fmaxf(sacc[mg][nt][0], sacc[mg][nt][1]));
                tm1 = fmaxf(tm1, fmaxf(sacc[mg][nt][2], sacc[mg][nt][3]));
            }
            tm0 = fmaxf(tm0, __shfl_xor_sync(0xffffffffu, tm0, 1));
            tm0 = fmaxf(tm0, __shfl_xor_sync(0xffffffffu, tm0, 2));
            tm1 = fmaxf(tm1, __shfl_xor_sync(0xffffffffu, tm1, 1));
            tm1 = fmaxf(tm1, __shfl_xor_sync(0xffffffffu, tm1, 2));

            const float mn0 = fmaxf(m[mg][0], tm0);
            const float mn1 = fmaxf(m[mg][1], tm1);
            const float corr0 = __expf(m[mg][0] - mn0);
            const float corr1 = __expf(m[mg][1] - mn1);
            m[mg][0] = mn0; m[mg][1] = mn1;

            float sum0 = 0.f, sum1 = 0.f;
#pragma unroll
            for (int nt = 0; nt < 8; nt++) {
                const float p00 = __expf(sacc[mg][nt][0] - mn0);
                const float p01 = __expf(sacc[mg][nt][1] - mn0);
                const float p10 = __expf(sacc[mg][nt][2] - mn1);
                const float p11 = __expf(sacc[mg][nt][3] - mn1);
                sum0 += p00 + p01;
                sum1 += p10 + p11;
                pk01[mg][nt] = pack_h2(p00, p01);
                pk23[mg][nt] = pack_h2(p10, p11);
            }
            sum0 += __shfl_xor_sync(0xffffffffu, sum0, 1);
            sum0 += __shfl_xor_sync(0xffffffffu, sum0, 2);
            sum1 += __shfl_xor_sync(0xffffffffu, sum1, 1);
            sum1 += __shfl_xor_sync(0xffffffffu, sum1, 2);
            l[mg][0] = l[mg][0] * corr0 + sum0;
            l[mg][1] = l[mg][1] * corr1 + sum1;

#pragma unroll
            for (int nt = 0; nt < 8; nt++) {
                oacc[mg][nt][0] *= corr0;
                oacc[mg][nt][1] *= corr0;
                oacc[mg][nt][2] *= corr1;
                oacc[mg][nt][3] *= corr1;
            }
        }

#pragma unroll
        for (int kc = 0; kc < 4; kc++) {
            const int g = lane >> 3;
            const int li = lane & 7;
            const int vrow = kc * 16 + (g & 1) * 8 + li;
#pragma unroll
            for (int ntp = 0; ntp < 4; ntp++) {
                const int vcol = ntp * 16 + (g >> 1) * 8;
                unsigned r0, r1, r2, r3;
                ldsm_x4_trans(r0, r1, r2, r3, &vs[vrow * AP + vcol]);
#pragma unroll
                for (int mg = 0; mg < 2; mg++) {
                    mma_f16(oacc[mg][ntp * 2],
                            pk01[mg][2 * kc], pk23[mg][2 * kc],
                            pk01[mg][2 * kc + 1], pk23[mg][2 * kc + 1], r0, r1);
                    mma_f16(oacc[mg][ntp * 2 + 1],
                            pk01[mg][2 * kc], pk23[mg][2 * kc],
                            pk01[mg][2 * kc + 1], pk23[mg][2 * kc + 1], r2, r3);
                }
            }
        }
    }

    const int b = bh >> 4;
    const int h = bh & (H_ - 1);
#pragma unroll
    for (int mg = 0; mg < 2; mg++) {
        const float il0 = 1.0f / l[mg][0];
        const float il1 = 1.0f / l[mg][1];
        const int t0 = qt * 128 + wrow + mg * 16 + lrow;
        const int t1 = t0 + 8;
        const size_t base0 = ((size_t)(b * T_ + t0)) * D_ + h * DH_;
        const size_t base1 = ((size_t)(b * T_ + t1)) * D_ + h * DH_;
#pragma unroll
        for (int nt = 0; nt < 8; nt++) {
            const int c0 = nt * 8 + lk * 2;
            *(__half2*)&g_attnh[base0 + c0] =
                __floats2half2_rn(oacc[mg][nt][0] * il0, oacc[mg][nt][1] * il0);
            *(__half2*)&g_attnh[base1 + c0] =
                __floats2half2_rn(oacc[mg][nt][2] * il1, oacc[mg][nt][3] * il1);
        }
    }
}

// ---------------------------------------------------------------------------
// kernel_launch
// ---------------------------------------------------------------------------
extern "C" void kernel_launch(void* const* d_in, const int* in_sizes, int n_in,
                              void* d_out, int out_size)
{
    (void)in_sizes; (void)n_in; (void)out_size;
    const float* x     = (const float*)d_in[0];
    const float* qkv_w = (const float*)d_in[2];
    const float* out_w = (const float*)d_in[3];
    const float* out_b = (const float*)d_in[4];
    float* out = (float*)d_out;

    void *p_xh, *p_w1t, *p_w2t, *p_attnh;
    cudaGetSymbolAddress(&p_xh, g_xh);
    cudaGetSymbolAddress(&p_w1t, g_w1t);
    cudaGetSymbolAddress(&p_w2t, g_w2t);
    cudaGetSymbolAddress(&p_attnh, g_attnh);

    cudaFuncSetAttribute(gemm_fp16,
                         cudaFuncAttributeMaxDynamicSharedMemorySize, GEMM_SMEM);
    cudaFuncSetAttribute(attn_fp16_kernel,
                         cudaFuncAttributeMaxDynamicSharedMemorySize, ATTN_SMEM);

    // 0) prep: x -> fp16, weights -> fp16 transposed [N][K], rope table
    to_half_kernel<<<(NROW * D_) / 1024, 256>>>(x, (__half*)p_xh);
    transpose_to_half<<<dim3(3 * D_ / 32, D_ / 32), dim3(32, 8)>>>(
        qkv_w, (__half*)p_w1t, D_, 3 * D_);
    transpose_to_half<<<dim3(D_ / 32, D_ / 32), dim3(32, 8)>>>(
        out_w, (__half*)p_w2t, D_, D_);
    rope_table_kernel<<<(T_ * 32) / 256, 256>>>();

    // 1) QKV projection with fused RoPE + q/k/v scatter (mode 1)
    gemm_fp16<<<dim3((3 * D_) / 128, NROW / 128), 128, GEMM_SMEM>>>(
        (const __half*)p_xh, (const __half*)p_w1t, nullptr, nullptr,
        1, NROW, 3 * D_, D_);

    // 2) causal flash attention (fp16 tensor cores)
    attn_fp16_kernel<<<dim3(T_ / 128, BH_), 128, ATTN_SMEM>>>();

    // 3) output projection + bias -> f32 (mode 0)
    gemm_fp16<<<dim3(D_ / 128, NROW / 128), 128, GEMM_SMEM>>>(
        (const __half*)p_attnh, (const __half*)p_w2t, out_b, out,
        0, NROW, D_, D_);
}